// round 7
// baseline (speedup 1.0000x reference)
#include <cuda_runtime.h>
#include <cstdint>
#include <cstddef>

#define HD 1024
#define NB 128
#define NS 128
#define NROW (NB*NS)
#define NCTA_SCAN 128
#define TILE_B 16384            // 128x32 swizzled tf32 tile
#define TILE_A 32768            // 256x32 swizzled tf32 tile
#define GEMM_SMEM (3*TILE_A + 3*TILE_B)  // 147456
#define OUT_SMEM  (6*TILE_B)             // 98304
#define SCAN_SMEM (8*TILE_B)             // 131072

// ---------------- scratch ----------------
__device__ __align__(16) float g_FR[(size_t)NS*NB*HD];
__device__ __align__(16) float g_FW[(size_t)NS*NB*HD];
__device__ __align__(16) unsigned g_Ctf[NB*HD];
__device__ __align__(16) float g_Otmp[NB*HD];
__device__ __align__(16) float g_part[(size_t)NCTA_SCAN*128*128];
__device__ __align__(16) float g_Glogit[NROW];
__device__ __align__(16) float g_Gt[NS*NB];
// pre-converted tf32 operands
__device__ __align__(16) unsigned g_ftf[(size_t)NB*NS*HD];
__device__ __align__(16) unsigned g_ztf[(size_t)NROW*4*HD];
__device__ __align__(16) unsigned g_Wz1tf[(size_t)HD*4*HD];
__device__ __align__(16) unsigned g_Wrtf[(size_t)HD*HD];
__device__ __align__(16) unsigned g_Wtf[(size_t)HD*HD];
__device__ __align__(16) unsigned g_Wmtf[(size_t)HD*3*HD];
__device__ __align__(16) unsigned g_pmtf[NB*HD];
__device__ __align__(16) unsigned g_qtf[NB*HD];
__device__ __align__(16) unsigned g_flags[NCTA_SCAN*32];

// ---------------- helpers ----------------
__device__ __forceinline__ unsigned f2tf(float f){
    unsigned u; asm("cvt.rna.tf32.f32 %0, %1;" : "=r"(u) : "f"(f)); return u;
}
__device__ __forceinline__ uint32_t smem_u32(const void* p){
    uint32_t a; asm("{ .reg .u64 t; cvta.to.shared.u64 t, %1; cvt.u32.u64 %0, t; }"
                    : "=r"(a) : "l"(p)); return a;
}
__device__ __forceinline__ void cpa16(uint32_t dst, const void* src){
    asm volatile("cp.async.cg.shared.global [%0], [%1], 16;" :: "r"(dst), "l"(src));
}
#define CP_COMMIT() asm volatile("cp.async.commit_group;" ::: "memory")
#define CP_WAIT(n)  asm volatile("cp.async.wait_group %0;" :: "n"(n) : "memory")

__device__ __forceinline__ unsigned ldcg_u32(const unsigned* p){
    unsigned v; asm volatile("ld.global.cg.u32 %0, [%1];" : "=r"(v) : "l"(p)); return v;
}
__device__ __forceinline__ void stcg_u32(unsigned* p, unsigned v){
    asm volatile("st.global.cg.u32 [%0], %1;" :: "l"(p), "r"(v) : "memory");
}
__device__ __forceinline__ void ldsm4(unsigned* r, uint32_t addr){
    asm volatile("ldmatrix.sync.aligned.m8n8.x4.shared.b16 {%0,%1,%2,%3}, [%4];"
        : "=r"(r[0]),"=r"(r[1]),"=r"(r[2]),"=r"(r[3]) : "r"(addr));
}
__device__ __forceinline__ void mma8(float* d, const unsigned* a, const unsigned* b){
    asm volatile("mma.sync.aligned.m16n8k8.row.col.f32.tf32.tf32.f32 "
        "{%0,%1,%2,%3},{%4,%5,%6,%7},{%8,%9},{%0,%1,%2,%3};\n"
        : "+f"(d[0]),"+f"(d[1]),"+f"(d[2]),"+f"(d[3])
        : "r"(a[0]),"r"(a[1]),"r"(a[2]),"r"(a[3]),"r"(b[0]),"r"(b[1]));
}

__device__ __forceinline__ void compute32s(uint32_t aBase, uint32_t bBase,
        const uint32_t* RA, const uint32_t* RB, const uint32_t* T, float acc[2][8][4]){
    #pragma unroll
    for (int ks = 0; ks < 4; ks++){
        unsigned a0[4], a1[4], bb[4][4];
        ldsm4(a0, aBase + RA[0] + T[ks]);
        ldsm4(a1, aBase + RA[1] + T[ks]);
        #pragma unroll
        for (int p = 0; p < 4; p++) ldsm4(bb[p], bBase + RB[p] + T[ks]);
        #pragma unroll
        for (int mi = 0; mi < 2; mi++){
            const unsigned* a = mi ? a1 : a0;
            #pragma unroll
            for (int p = 0; p < 4; p++){
                unsigned b0[2] = {bb[p][0], bb[p][2]};
                unsigned b1[2] = {bb[p][1], bb[p][3]};
                mma8(acc[mi][2*p],   a, b0);
                mma8(acc[mi][2*p+1], a, b1);
            }
        }
    }
}

#define LDSM_OFFSETS() \
    int swl = lane & 7, hlf = (lane >> 4) & 1; \
    int rowA0 = warp_m + (lane & 7) + ((lane >> 3) & 1)*8; \
    uint32_t RA[2] = { (uint32_t)rowA0*128u, (uint32_t)(rowA0+16)*128u }; \
    uint32_t RB[4]; \
    _Pragma("unroll") for (int p_ = 0; p_ < 4; p_++) \
        RB[p_] = (uint32_t)(warp_n + p_*16 + (lane & 15))*128u; \
    uint32_t T[4]; \
    _Pragma("unroll") for (int k_ = 0; k_ < 4; k_++) \
        T[k_] = (uint32_t)(((k_*2 + hlf) ^ swl)*16);

#define ZERO_ACC(acc) { \
    _Pragma("unroll") for (int _i=0;_i<2;_i++) \
    _Pragma("unroll") for (int _j=0;_j<8;_j++) \
    _Pragma("unroll") for (int _k=0;_k<4;_k++) acc[_i][_j][_k]=0.f; }

// 512-thread loader: A 256 rows (4x16B/thread), B 128 rows (2x16B/thread)
#define GEMM_CP512(i_, st_, Abase_, Alds_, Bbase_, Blds_) { \
    int kc_ = (i_)*32; \
    _Pragma("unroll") for (int j = 0; j < 4; j++){ int r_ = rb + j*64; \
        cpa16(sbase + (st_)*TILE_A + r_*128 + swz16, \
              (Abase_) + (size_t)r_*(Alds_) + kc_ + c4v); } \
    _Pragma("unroll") for (int j = 0; j < 2; j++){ int r_ = rb + j*64; \
        cpa16(sbase + 3*TILE_A + (st_)*TILE_B + r_*128 + swz16, \
              (Bbase_) + (size_t)r_*(Blds_) + kc_ + c4v); } \
    CP_COMMIT(); }

// 256-thread loader: A 128 rows + B 128 rows (4x16B each)
#define GEMM_CP256(i_, st_, Abase_, Alds_, Bbase_, Blds_) { \
    int kc_ = (i_)*32; \
    _Pragma("unroll") for (int j = 0; j < 4; j++){ int r_ = rb + j*32; \
        cpa16(sbase + (st_)*TILE_B + r_*128 + swz16, \
              (Abase_) + (size_t)r_*(Alds_) + kc_ + c4v); \
        cpa16(sbase + (3 + (st_))*TILE_B + r_*128 + swz16, \
              (Bbase_) + (size_t)r_*(Blds_) + kc_ + c4v); } CP_COMMIT(); }

// ---------------- K0: per-replay init ----------------
__global__ void k_init(){
    int i = blockIdx.x * blockDim.x + threadIdx.x;
    if (i < NCTA_SCAN*32) g_flags[i] = 0u;
    if (i < NROW) g_Glogit[i] = 0.f;
    if (i < NB*HD){ g_Ctf[i] = 0u; g_Otmp[i] = 0.f; }
}

// ---------------- Kc: fp32 -> tf32 bulk convert ----------------
__global__ void k_cvt(const float4* __restrict__ src, uint4* __restrict__ dst, int n4){
    for (int i = blockIdx.x*blockDim.x + threadIdx.x; i < n4; i += gridDim.x*blockDim.x){
        float4 v = src[i];
        dst[i] = make_uint4(f2tf(v.x), f2tf(v.y), f2tf(v.z), f2tf(v.w));
    }
}

// ---------------- Kz: build z (tf32) ----------------
__global__ void k_zb(const float* __restrict__ facts, const float* __restrict__ q,
                     const float* __restrict__ pm){
    int row = blockIdx.x;           // bt*NS + s
    int bt = row >> 7;
    int t = threadIdx.x;
    float4 f  = *reinterpret_cast<const float4*>(facts + (size_t)row*HD + t*4);
    float4 qv = *reinterpret_cast<const float4*>(q  + (size_t)bt*HD + t*4);
    float4 mv = *reinterpret_cast<const float4*>(pm + (size_t)bt*HD + t*4);
    unsigned* zr = g_ztf + (size_t)row*(4*HD);
    uint4 o;
    o = make_uint4(f2tf(f.x*qv.x), f2tf(f.y*qv.y), f2tf(f.z*qv.z), f2tf(f.w*qv.w));
    *reinterpret_cast<uint4*>(zr + 0*HD + t*4) = o;
    o = make_uint4(f2tf(f.x*mv.x), f2tf(f.y*mv.y), f2tf(f.z*mv.z), f2tf(f.w*mv.w));
    *reinterpret_cast<uint4*>(zr + 1*HD + t*4) = o;
    o = make_uint4(f2tf(fabsf(f.x-qv.x)), f2tf(fabsf(f.y-qv.y)), f2tf(fabsf(f.z-qv.z)), f2tf(fabsf(f.w-qv.w)));
    *reinterpret_cast<uint4*>(zr + 2*HD + t*4) = o;
    o = make_uint4(f2tf(fabsf(f.x-mv.x)), f2tf(fabsf(f.y-mv.y)), f2tf(fabsf(f.z-mv.z)), f2tf(fabsf(f.w-mv.w)));
    *reinterpret_cast<uint4*>(zr + 3*HD + t*4) = o;
}

// ================= K1: G logits (M=256 tiles, 512 threads) =================
__global__ void __launch_bounds__(512,1) k6_G(
        const float* __restrict__ bz1, const float* __restrict__ Wz2){
    extern __shared__ unsigned us[];
    uint32_t sbase = smem_u32(us);
    int tid = threadIdx.x, wid = tid >> 5, lane = tid & 31;
    int lg = lane >> 2, lk = lane & 3;
    int warp_m = (wid >> 1) * 32, warp_n = (wid & 1) * 64;
    int nt = blockIdx.x, mt = blockIdx.y;   // mt: 256-row slab (= 2 batches)
    int c4v = (tid & 7) * 4, rb = tid >> 3;  // rb in [0,64)
    uint32_t swz16 = (uint32_t)(((tid & 7) ^ (rb & 7)) * 16);
    LDSM_OFFSETS();
    // row mt*256 + r maps linearly: bt*NS + s = mt*256 + r
    const unsigned* Ab = g_ztf + (size_t)(mt*256)*(4*HD);
    const unsigned* Bb = g_Wz1tf + (size_t)(nt*128)*(4*HD);
    float acc[2][8][4]; ZERO_ACC(acc);

    const int NBLK = 128;
    GEMM_CP512(0, 0, Ab, 4*HD, Bb, 4*HD);
    GEMM_CP512(1, 1, Ab, 4*HD, Bb, 4*HD);
    int st = 0;
    for (int i = 0; i < NBLK; i++){
        CP_WAIT(1);
        __syncthreads();
        if (i + 2 < NBLK){
            int st2 = st + 2; if (st2 >= 3) st2 -= 3;
            GEMM_CP512(i+2, st2, Ab, 4*HD, Bb, 4*HD);
        }
        compute32s(sbase + st*TILE_A, sbase + 3*TILE_A + st*TILE_B, RA, RB, T, acc);
        if (++st == 3) st = 0;
    }

    float rs[4] = {0.f, 0.f, 0.f, 0.f};
    #pragma unroll
    for (int mi = 0; mi < 2; mi++)
        #pragma unroll
        for (int ni = 0; ni < 8; ni++){
            int c0 = nt*128 + warp_n + ni*8 + lk*2;
            float w0 = Wz2[c0], w1 = Wz2[c0+1];
            float z0 = bz1[c0], z1 = bz1[c0+1];
            rs[mi*2+0] += tanhf(acc[mi][ni][0]+z0)*w0 + tanhf(acc[mi][ni][1]+z1)*w1;
            rs[mi*2+1] += tanhf(acc[mi][ni][2]+z0)*w0 + tanhf(acc[mi][ni][3]+z1)*w1;
        }
    #pragma unroll
    for (int r = 0; r < 4; r++){
        rs[r] += __shfl_xor_sync(0xffffffffu, rs[r], 1);
        rs[r] += __shfl_xor_sync(0xffffffffu, rs[r], 2);
    }
    if (lk == 0){
        int r0 = mt*256 + warp_m + lg;
        atomicAdd(&g_Glogit[r0     ], rs[0]);
        atomicAdd(&g_Glogit[r0 + 8 ], rs[1]);
        atomicAdd(&g_Glogit[r0 + 16], rs[2]);
        atomicAdd(&g_Glogit[r0 + 24], rs[3]);
    }
}

// ================= K3: FR/FW (M=256 tiles, 512 threads) =================
__global__ void __launch_bounds__(512,1) k6_F(
        const float* __restrict__ br, const float* __restrict__ bw){
    extern __shared__ unsigned us[];
    uint32_t sbase = smem_u32(us);
    int tid = threadIdx.x, wid = tid >> 5, lane = tid & 31;
    int lg = lane >> 2, lk = lane & 3;
    int warp_m = (wid >> 1) * 32, warp_n = (wid & 1) * 64;
    int nt = blockIdx.x, mt = blockIdx.y, which = blockIdx.z;
    const unsigned* Wtf  = which ? g_Wtf : g_Wrtf;
    const float*    bsel = which ? bw : br;
    float* Out = which ? g_FW : g_FR;
    int c4v = (tid & 7) * 4, rb = tid >> 3;
    uint32_t swz16 = (uint32_t)(((tid & 7) ^ (rb & 7)) * 16);
    LDSM_OFFSETS();
    const unsigned* Ab = g_ftf + (size_t)(mt*256)*HD;
    const unsigned* Bb = Wtf + (size_t)(nt*128)*HD;
    float acc[2][8][4]; ZERO_ACC(acc);

    const int NBLK = 32;
    GEMM_CP512(0, 0, Ab, HD, Bb, HD);
    GEMM_CP512(1, 1, Ab, HD, Bb, HD);
    int st = 0;
    for (int i = 0; i < NBLK; i++){
        CP_WAIT(1);
        __syncthreads();
        if (i + 2 < NBLK){
            int st2 = st + 2; if (st2 >= 3) st2 -= 3;
            GEMM_CP512(i+2, st2, Ab, HD, Bb, HD);
        }
        compute32s(sbase + st*TILE_A, sbase + 3*TILE_A + st*TILE_B, RA, RB, T, acc);
        if (++st == 3) st = 0;
    }

    #pragma unroll
    for (int mi = 0; mi < 2; mi++){
        int r0 = warp_m + mi*16 + lg;           // 0..255
        int s = r0 & 127, bt = mt*2 + (r0 >> 7);
        #pragma unroll
        for (int ni = 0; ni < 8; ni++){
            int h = nt*128 + warp_n + ni*8 + lk*2;
            float b0 = bsel[h], b1 = bsel[h+1];
            float2 v0 = make_float2(acc[mi][ni][0]+b0, acc[mi][ni][1]+b1);
            float2 v1 = make_float2(acc[mi][ni][2]+b0, acc[mi][ni][3]+b1);
            *reinterpret_cast<float2*>(Out + (size_t)s*(NB*HD) + (size_t)bt*HD + h) = v0;
            *reinterpret_cast<float2*>(Out + (size_t)(s+8)*(NB*HD) + (size_t)bt*HD + h) = v1;
        }
    }
}

// ---------------- K2: softmax ----------------
__global__ void k_softmax(){
    int bt = blockIdx.x, t = threadIdx.x;
    float v = g_Glogit[bt*NS + t];
    __shared__ float sm_[4], ss[4];
    float mx = v;
    #pragma unroll
    for (int o = 16; o; o >>= 1) mx = fmaxf(mx, __shfl_xor_sync(0xffffffffu, mx, o));
    if ((t & 31) == 0) sm_[t >> 5] = mx;
    __syncthreads();
    mx = fmaxf(fmaxf(sm_[0], sm_[1]), fmaxf(sm_[2], sm_[3]));
    float e = __expf(v - mx);
    float sum = e;
    #pragma unroll
    for (int o = 16; o; o >>= 1) sum += __shfl_xor_sync(0xffffffffu, sum, o);
    if ((t & 31) == 0) ss[t >> 5] = sum;
    __syncthreads();
    sum = ss[0] + ss[1] + ss[2] + ss[3];
    g_Gt[t*NB + bt] = e / sum;
}

// ---------------- K4: persistent scan ----------------
__device__ __forceinline__ void gsync(unsigned step, int tid, int cta){
    __syncthreads();
    if (tid == 0){
        __threadfence();
        stcg_u32(&g_flags[cta*32], step);
    }
    if (tid < NCTA_SCAN){
        while (ldcg_u32(&g_flags[tid*32]) < step) { }
    }
    __threadfence();
    __syncthreads();
}
__device__ __forceinline__ float gru_upd(float fr, float fw, float y1, float y2,
                                         float b_ur, float b_u, float c, float g){
    float r  = 1.f / (1.f + __expf(-(fr + y1 + b_ur)));
    float ht = tanhf(fw + r * (y2 + b_u));
    return g * ht + (1.f - g) * c;
}

__global__ void __launch_bounds__(256,1) k6_scan(
        const float* __restrict__ Ur, const float* __restrict__ bur,
        const float* __restrict__ U,  const float* __restrict__ bu){
    extern __shared__ unsigned us[];   // A subs: tiles 0-3; B resident: tiles 4-7
    uint32_t sbase = smem_u32(us);
    char* sc = reinterpret_cast<char*>(us);
    int cta = blockIdx.x, tid = threadIdx.x;
    int wid = tid >> 5, lane = tid & 31, lg = lane >> 2, lk = lane & 3;
    int warp_m = (wid >> 1) * 32, warp_n = (wid & 1) * 64;
    int c4v = (tid & 7) * 4, rb = tid >> 3;
    uint32_t swz16 = (uint32_t)(((tid & 7) ^ (rb & 7)) * 16);
    LDSM_OFFSETS();
    int nt = cta >> 3;
    int kcb = (cta & 7) * 128;
    const float* Wsel = (nt < 8) ? Ur : U;
    int nbase = (nt & 7) * 128;
    float* P = g_part + (size_t)cta * 16384;

    // resident tf32 weights in swizzled tiles 4..7
    #pragma unroll
    for (int j = 0; j < 16; j++){
        int s = j >> 2, n = rb + (j & 3)*32;
        float4 v = *reinterpret_cast<const float4*>(Wsel + (size_t)(nbase+n)*HD + kcb + s*32 + c4v);
        uint4 o = make_uint4(f2tf(v.x), f2tf(v.y), f2tf(v.z), f2tf(v.w));
        *reinterpret_cast<uint4*>(sc + (4+s)*TILE_B + n*128 + swz16) = o;
    }
    __syncthreads();

    int e  = (cta*256 + tid) * 4;
    int eb = e >> 10, eh = e & (HD-1);
    int nt1 = eh >> 7, hm = eh & 127;
    float4 vur = *reinterpret_cast<const float4*>(bur + eh);
    float4 vu  = *reinterpret_cast<const float4*>(bu + eh);
    float4 creg = make_float4(0.f, 0.f, 0.f, 0.f);   // own C elements, in registers

    unsigned bar = 0;
    for (int s = 0; s < NS; s++){
        float4 fr = *reinterpret_cast<const float4*>(g_FR + (size_t)s*NB*HD + (size_t)eb*HD + eh);
        float4 fw = *reinterpret_cast<const float4*>(g_FW + (size_t)s*NB*HD + (size_t)eb*HD + eh);
        float gg = g_Gt[s*NB + eb];

        #pragma unroll
        for (int sg = 0; sg < 4; sg++){
            #pragma unroll
            for (int j = 0; j < 4; j++){
                int r = rb + j*32;
                cpa16(sbase + sg*TILE_B + r*128 + swz16,
                      g_Ctf + (size_t)r*HD + kcb + sg*32 + c4v);
            }
            CP_COMMIT();
        }
        float acc[2][8][4]; ZERO_ACC(acc);
        #pragma unroll
        for (int sub = 0; sub < 4; sub++){
            if (sub == 0)      CP_WAIT(3);
            else if (sub == 1) CP_WAIT(2);
            else if (sub == 2) CP_WAIT(1);
            else               CP_WAIT(0);
            __syncthreads();
            compute32s(sbase + sub*TILE_B, sbase + (4+sub)*TILE_B, RA, RB, T, acc);
        }
        #pragma unroll
        for (int mi = 0; mi < 2; mi++){
            int r0 = warp_m + mi*16 + lg;
            #pragma unroll
            for (int ni = 0; ni < 8; ni++){
                int c = warp_n + ni*8 + lk*2;
                __stcg(reinterpret_cast<float2*>(P + r0*128 + c),
                       make_float2(acc[mi][ni][0], acc[mi][ni][1]));
                __stcg(reinterpret_cast<float2*>(P + (r0+8)*128 + c),
                       make_float2(acc[mi][ni][2], acc[mi][ni][3]));
            }
        }
        gsync(++bar, tid, cta);

        float4 y1 = make_float4(0,0,0,0), y2 = make_float4(0,0,0,0);
        #pragma unroll
        for (int kk = 0; kk < 8; kk++){
            float4 p1 = __ldcg(reinterpret_cast<const float4*>(
                g_part + (size_t)(nt1*8 + kk)*16384 + eb*128 + hm));
            float4 p2 = __ldcg(reinterpret_cast<const float4*>(
                g_part + (size_t)((nt1+8)*8 + kk)*16384 + eb*128 + hm));
            y1.x += p1.x; y1.y += p1.y; y1.z += p1.z; y1.w += p1.w;
            y2.x += p2.x; y2.y += p2.y; y2.z += p2.z; y2.w += p2.w;
        }
        creg.x = gru_upd(fr.x, fw.x, y1.x, y2.x, vur.x, vu.x, creg.x, gg);
        creg.y = gru_upd(fr.y, fw.y, y1.y, y2.y, vur.y, vu.y, creg.y, gg);
        creg.z = gru_upd(fr.z, fw.z, y1.z, y2.z, vur.z, vu.z, creg.z, gg);
        creg.w = gru_upd(fr.w, fw.w, y1.w, y2.w, vur.w, vu.w, creg.w, gg);
        uint4 ct;
        ct.x = f2tf(creg.x); ct.y = f2tf(creg.y); ct.z = f2tf(creg.z); ct.w = f2tf(creg.w);
        __stcg(reinterpret_cast<uint4*>(g_Ctf + (size_t)eb*HD + eh), ct);
        gsync(++bar, tid, cta);
    }
}

// ---------------- K5: final GEMM (pipelined split-K) ----------------
__global__ void __launch_bounds__(256,2) k6_out(){
    extern __shared__ unsigned us[];
    uint32_t sbase = smem_u32(us);
    int tid = threadIdx.x, wid = tid >> 5, lane = tid & 31;
    int lg = lane >> 2, lk = lane & 3;
    int warp_m = (wid >> 1) * 32, warp_n = (wid & 1) * 64;
    int nt = blockIdx.x, ks = blockIdx.y;   // ks in [0,12): seg = ks>>2
    int c4v = (tid & 7) * 4, rb = tid >> 3;
    uint32_t swz16 = (uint32_t)(((tid & 7) ^ (rb & 7)) * 16);
    LDSM_OFFSETS();
    int seg = ks >> 2;
    const unsigned* Ab = (seg == 0) ? g_pmtf : (seg == 1 ? g_Ctf : g_qtf);
    Ab += (ks & 3) * 256;                                    // column offset in [0,1024)
    const unsigned* Bb = g_Wmtf + (size_t)(nt*128)*(3*HD) + ks*256;
    float acc[2][8][4]; ZERO_ACC(acc);

    const int NBLK = 8;
    GEMM_CP256(0, 0, Ab, HD, Bb, 3*HD);
    GEMM_CP256(1, 1, Ab, HD, Bb, 3*HD);
    int st = 0;
    for (int i = 0; i < NBLK; i++){
        CP_WAIT(1);
        __syncthreads();
        if (i + 2 < NBLK){
            int st2 = st + 2; if (st2 >= 3) st2 -= 3;
            GEMM_CP256(i+2, st2, Ab, HD, Bb, 3*HD);
        }
        compute32s(sbase + st*TILE_B, sbase + (3+st)*TILE_B, RA, RB, T, acc);
        if (++st == 3) st = 0;
    }
    #pragma unroll
    for (int mi = 0; mi < 2; mi++){
        int r0 = warp_m + mi*16 + lg;
        #pragma unroll
        for (int ni = 0; ni < 8; ni++){
            int h = nt*128 + warp_n + ni*8 + lk*2;
            atomicAdd(&g_Otmp[(size_t)r0*HD + h     ], acc[mi][ni][0]);
            atomicAdd(&g_Otmp[(size_t)r0*HD + h + 1 ], acc[mi][ni][1]);
            atomicAdd(&g_Otmp[(size_t)(r0+8)*HD + h    ], acc[mi][ni][2]);
            atomicAdd(&g_Otmp[(size_t)(r0+8)*HD + h + 1], acc[mi][ni][3]);
        }
    }
}

// ---------------- K6: bias + relu ----------------
__global__ void k_finish(const float* __restrict__ bm, float* __restrict__ out){
    int i = blockIdx.x * blockDim.x + threadIdx.x;
    if (i < NB*HD){
        float v = g_Otmp[i] + bm[i & (HD-1)];
        out[i] = fmaxf(v, 0.f);
    }
}

// ---------------- launch ----------------
extern "C" void kernel_launch(void* const* d_in, const int* in_sizes, int n_in,
                              void* d_out, int out_size){
    (void)in_sizes; (void)n_in; (void)out_size;
    const float* facts     = (const float*)d_in[0];
    const float* questions = (const float*)d_in[1];
    const float* prevM     = (const float*)d_in[2];
    const float* Wr  = (const float*)d_in[3];
    const float* br  = (const float*)d_in[4];
    const float* Ur  = (const float*)d_in[5];
    const float* bur = (const float*)d_in[6];
    const float* W   = (const float*)d_in[7];
    const float* bw  = (const float*)d_in[8];
    const float* U   = (const float*)d_in[9];
    const float* bu  = (const float*)d_in[10];
    const float* Wz1 = (const float*)d_in[11];
    const float* bz1 = (const float*)d_in[12];
    const float* Wz2 = (const float*)d_in[13];
    // d_in[14] = bz2: softmax shift-invariant, cancels.
    const float* Wm  = (const float*)d_in[15];
    const float* bm  = (const float*)d_in[16];
    float* out = (float*)d_out;

    static int attr_done = 0;
    if (!attr_done){
        cudaFuncSetAttribute(k6_G,    cudaFuncAttributeMaxDynamicSharedMemorySize, GEMM_SMEM);
        cudaFuncSetAttribute(k6_F,    cudaFuncAttributeMaxDynamicSharedMemorySize, GEMM_SMEM);
        cudaFuncSetAttribute(k6_scan, cudaFuncAttributeMaxDynamicSharedMemorySize, SCAN_SMEM);
        cudaFuncSetAttribute(k6_out,  cudaFuncAttributeMaxDynamicSharedMemorySize, OUT_SMEM);
        attr_done = 1;
    }

    unsigned* dWz1tf; cudaGetSymbolAddress((void**)&dWz1tf, g_Wz1tf);
    unsigned* dWrtf;  cudaGetSymbolAddress((void**)&dWrtf,  g_Wrtf);
    unsigned* dWtf;   cudaGetSymbolAddress((void**)&dWtf,   g_Wtf);
    unsigned* dftf;   cudaGetSymbolAddress((void**)&dftf,   g_ftf);
    unsigned* dWmtf;  cudaGetSymbolAddress((void**)&dWmtf,  g_Wmtf);
    unsigned* dpmtf;  cudaGetSymbolAddress((void**)&dpmtf,  g_pmtf);
    unsigned* dqtf;   cudaGetSymbolAddress((void**)&dqtf,   g_qtf);

    k_init<<<512, 256>>>();
    k_cvt<<<2048, 256>>>((const float4*)facts, (uint4*)dftf,   (NB*NS*HD)/4);
    k_cvt<<<1024, 256>>>((const float4*)Wz1,   (uint4*)dWz1tf, (HD*4*HD)/4);
    k_cvt<<<512, 256>>>((const float4*)Wr,     (uint4*)dWrtf,  (HD*HD)/4);
    k_cvt<<<512, 256>>>((const float4*)W,      (uint4*)dWtf,   (HD*HD)/4);
    k_cvt<<<1024, 256>>>((const float4*)Wm,    (uint4*)dWmtf,  (HD*3*HD)/4);
    k_cvt<<<128, 256>>>((const float4*)prevM,  (uint4*)dpmtf,  (NB*HD)/4);
    k_cvt<<<128, 256>>>((const float4*)questions, (uint4*)dqtf, (NB*HD)/4);
    k_zb<<<NROW, 256>>>(facts, questions, prevM);
    dim3 gG(8, 64);
    k6_G<<<gG, 512, GEMM_SMEM>>>(bz1, Wz2);
    k_softmax<<<128, 128>>>();
    dim3 gF(8, 64, 2);
    k6_F<<<gF, 512, GEMM_SMEM>>>(br, bw);
    k6_scan<<<NCTA_SCAN, 256, SCAN_SMEM>>>(Ur, bur, U, bu);
    dim3 gO(8, 12);
    k6_out<<<gO, 256, OUT_SMEM>>>();
    k_finish<<<512, 256>>>(bm, out);
}

// round 8
// speedup vs baseline: 1.0814x; 1.0814x over previous
#include <cuda_runtime.h>
#include <cstdint>
#include <cstddef>

#define HD 1024
#define NB 128
#define NS 128
#define NROW (NB*NS)
#define NCTA_SCAN 128
#define TILE_B 16384            // 128x32 swizzled tf32 tile
#define GEMM_SMEM (6*TILE_B)    // 98304: 3xA + 3xB  (2 CTAs/SM)
#define SCAN_SMEM (8*TILE_B)    // 131072

// ---------------- scratch ----------------
__device__ __align__(16) float g_FR[(size_t)NS*NB*HD];
__device__ __align__(16) float g_FW[(size_t)NS*NB*HD];
__device__ __align__(16) unsigned g_Ctf[NB*HD];
__device__ __align__(16) float g_Otmp[NB*HD];
__device__ __align__(16) float g_part[(size_t)NCTA_SCAN*128*128];
__device__ __align__(16) float g_Glogit[NROW];
__device__ __align__(16) float g_Gt[NS*NB];
// pre-converted tf32 operands
__device__ __align__(16) unsigned g_ftf[(size_t)NB*NS*HD];
__device__ __align__(16) unsigned g_ztf[(size_t)NROW*4*HD];
__device__ __align__(16) unsigned g_Wz1tf[(size_t)HD*4*HD];
__device__ __align__(16) unsigned g_Wrtf[(size_t)HD*HD];
__device__ __align__(16) unsigned g_Wtf[(size_t)HD*HD];
__device__ __align__(16) unsigned g_Wmtf[(size_t)HD*3*HD];
__device__ __align__(16) unsigned g_pmtf[NB*HD];
__device__ __align__(16) unsigned g_qtf[NB*HD];
__device__ __align__(16) unsigned g_flags[NCTA_SCAN*32];

// ---------------- helpers ----------------
__device__ __forceinline__ unsigned f2tf(float f){
    unsigned u; asm("cvt.rna.tf32.f32 %0, %1;" : "=r"(u) : "f"(f)); return u;
}
__device__ __forceinline__ uint32_t smem_u32(const void* p){
    uint32_t a; asm("{ .reg .u64 t; cvta.to.shared.u64 t, %1; cvt.u32.u64 %0, t; }"
                    : "=r"(a) : "l"(p)); return a;
}
__device__ __forceinline__ void cpa16(uint32_t dst, const void* src){
    asm volatile("cp.async.cg.shared.global [%0], [%1], 16;" :: "r"(dst), "l"(src));
}
#define CP_COMMIT() asm volatile("cp.async.commit_group;" ::: "memory")
#define CP_WAIT(n)  asm volatile("cp.async.wait_group %0;" :: "n"(n) : "memory")

__device__ __forceinline__ unsigned ldcg_u32(const unsigned* p){
    unsigned v; asm volatile("ld.global.cg.u32 %0, [%1];" : "=r"(v) : "l"(p)); return v;
}
__device__ __forceinline__ void stcg_u32(unsigned* p, unsigned v){
    asm volatile("st.global.cg.u32 [%0], %1;" :: "l"(p), "r"(v) : "memory");
}
__device__ __forceinline__ void ldsm4(unsigned* r, uint32_t addr){
    asm volatile("ldmatrix.sync.aligned.m8n8.x4.shared.b16 {%0,%1,%2,%3}, [%4];"
        : "=r"(r[0]),"=r"(r[1]),"=r"(r[2]),"=r"(r[3]) : "r"(addr));
}
__device__ __forceinline__ void mma8(float* d, const unsigned* a, const unsigned* b){
    asm volatile("mma.sync.aligned.m16n8k8.row.col.f32.tf32.tf32.f32 "
        "{%0,%1,%2,%3},{%4,%5,%6,%7},{%8,%9},{%0,%1,%2,%3};\n"
        : "+f"(d[0]),"+f"(d[1]),"+f"(d[2]),"+f"(d[3])
        : "r"(a[0]),"r"(a[1]),"r"(a[2]),"r"(a[3]),"r"(b[0]),"r"(b[1]));
}

__device__ __forceinline__ void compute32s(uint32_t aBase, uint32_t bBase,
        const uint32_t* RA, const uint32_t* RB, const uint32_t* T, float acc[2][8][4]){
    #pragma unroll
    for (int ks = 0; ks < 4; ks++){
        unsigned a0[4], a1[4], bb[4][4];
        ldsm4(a0, aBase + RA[0] + T[ks]);
        ldsm4(a1, aBase + RA[1] + T[ks]);
        #pragma unroll
        for (int p = 0; p < 4; p++) ldsm4(bb[p], bBase + RB[p] + T[ks]);
        #pragma unroll
        for (int mi = 0; mi < 2; mi++){
            const unsigned* a = mi ? a1 : a0;
            #pragma unroll
            for (int p = 0; p < 4; p++){
                unsigned b0[2] = {bb[p][0], bb[p][2]};
                unsigned b1[2] = {bb[p][1], bb[p][3]};
                mma8(acc[mi][2*p],   a, b0);
                mma8(acc[mi][2*p+1], a, b1);
            }
        }
    }
}

#define LDSM_OFFSETS() \
    int swl = lane & 7, hlf = (lane >> 4) & 1; \
    int rowA0 = warp_m + (lane & 7) + ((lane >> 3) & 1)*8; \
    uint32_t RA[2] = { (uint32_t)rowA0*128u, (uint32_t)(rowA0+16)*128u }; \
    uint32_t RB[4]; \
    _Pragma("unroll") for (int p_ = 0; p_ < 4; p_++) \
        RB[p_] = (uint32_t)(warp_n + p_*16 + (lane & 15))*128u; \
    uint32_t T[4]; \
    _Pragma("unroll") for (int k_ = 0; k_ < 4; k_++) \
        T[k_] = (uint32_t)(((k_*2 + hlf) ^ swl)*16);

#define ZERO_ACC(acc) { \
    _Pragma("unroll") for (int _i=0;_i<2;_i++) \
    _Pragma("unroll") for (int _j=0;_j<8;_j++) \
    _Pragma("unroll") for (int _k=0;_k<4;_k++) acc[_i][_j][_k]=0.f; }

// 256-thread loader: A 128 rows + B 128 rows (4x16B each)
#define GEMM_CP(i_, st_, Abase_, Alds_, Bbase_, Blds_) { \
    int kc_ = (i_)*32; \
    _Pragma("unroll") for (int j = 0; j < 4; j++){ int r_ = rb + j*32; \
        cpa16(sbase + (st_)*TILE_B + r_*128 + swz16, \
              (Abase_) + (size_t)r_*(Alds_) + kc_ + c4v); \
        cpa16(sbase + (3 + (st_))*TILE_B + r_*128 + swz16, \
              (Bbase_) + (size_t)r_*(Blds_) + kc_ + c4v); } CP_COMMIT(); }

// ---------------- K0: per-replay init ----------------
__global__ void k_init(){
    int i = blockIdx.x * blockDim.x + threadIdx.x;
    if (i < NCTA_SCAN*32) g_flags[i] = 0u;
    if (i < NROW) g_Glogit[i] = 0.f;
    if (i < NB*HD){ g_Ctf[i] = 0u; g_Otmp[i] = 0.f; }
}

// ---------------- Kc: fp32 -> tf32 bulk convert ----------------
__global__ void k_cvt(const float4* __restrict__ src, uint4* __restrict__ dst, int n4){
    for (int i = blockIdx.x*blockDim.x + threadIdx.x; i < n4; i += gridDim.x*blockDim.x){
        float4 v = src[i];
        dst[i] = make_uint4(f2tf(v.x), f2tf(v.y), f2tf(v.z), f2tf(v.w));
    }
}

// ---------------- Kz: build z (tf32) ----------------
__global__ void k_zb(const float* __restrict__ facts, const float* __restrict__ q,
                     const float* __restrict__ pm){
    int row = blockIdx.x;           // bt*NS + s
    int bt = row >> 7;
    int t = threadIdx.x;
    float4 f  = *reinterpret_cast<const float4*>(facts + (size_t)row*HD + t*4);
    float4 qv = *reinterpret_cast<const float4*>(q  + (size_t)bt*HD + t*4);
    float4 mv = *reinterpret_cast<const float4*>(pm + (size_t)bt*HD + t*4);
    unsigned* zr = g_ztf + (size_t)row*(4*HD);
    uint4 o;
    o = make_uint4(f2tf(f.x*qv.x), f2tf(f.y*qv.y), f2tf(f.z*qv.z), f2tf(f.w*qv.w));
    *reinterpret_cast<uint4*>(zr + 0*HD + t*4) = o;
    o = make_uint4(f2tf(f.x*mv.x), f2tf(f.y*mv.y), f2tf(f.z*mv.z), f2tf(f.w*mv.w));
    *reinterpret_cast<uint4*>(zr + 1*HD + t*4) = o;
    o = make_uint4(f2tf(fabsf(f.x-qv.x)), f2tf(fabsf(f.y-qv.y)), f2tf(fabsf(f.z-qv.z)), f2tf(fabsf(f.w-qv.w)));
    *reinterpret_cast<uint4*>(zr + 2*HD + t*4) = o;
    o = make_uint4(f2tf(fabsf(f.x-mv.x)), f2tf(fabsf(f.y-mv.y)), f2tf(fabsf(f.z-mv.z)), f2tf(fabsf(f.w-mv.w)));
    *reinterpret_cast<uint4*>(zr + 3*HD + t*4) = o;
}

// ================= K1: G logits (128x128 tiles, 2 CTAs/SM, triple buffer) =================
__global__ void __launch_bounds__(256,2) k7_G(
        const float* __restrict__ bz1, const float* __restrict__ Wz2){
    extern __shared__ unsigned us[];
    uint32_t sbase = smem_u32(us);
    int tid = threadIdx.x, wid = tid >> 5, lane = tid & 31;
    int lg = lane >> 2, lk = lane & 3;
    int warp_m = (wid >> 1) * 32, warp_n = (wid & 1) * 64;
    int nt = blockIdx.x, bt = blockIdx.y;
    int c4v = (tid & 7) * 4, rb = tid >> 3;
    uint32_t swz16 = (uint32_t)(((tid & 7) ^ (rb & 7)) * 16);
    LDSM_OFFSETS();
    const unsigned* Ab = g_ztf + (size_t)bt*NS*(4*HD);
    const unsigned* Bb = g_Wz1tf + (size_t)(nt*128)*(4*HD);
    float acc[2][8][4]; ZERO_ACC(acc);

    const int NBLK = 128;
    GEMM_CP(0, 0, Ab, 4*HD, Bb, 4*HD);
    GEMM_CP(1, 1, Ab, 4*HD, Bb, 4*HD);
    int st = 0;
    for (int i = 0; i < NBLK; i++){
        CP_WAIT(1);
        __syncthreads();
        if (i + 2 < NBLK){
            int st2 = st + 2; if (st2 >= 3) st2 -= 3;
            GEMM_CP(i+2, st2, Ab, 4*HD, Bb, 4*HD);
        }
        compute32s(sbase + st*TILE_B, sbase + (3+st)*TILE_B, RA, RB, T, acc);
        if (++st == 3) st = 0;
    }

    float rs[4] = {0.f, 0.f, 0.f, 0.f};
    #pragma unroll
    for (int mi = 0; mi < 2; mi++)
        #pragma unroll
        for (int ni = 0; ni < 8; ni++){
            int c0 = nt*128 + warp_n + ni*8 + lk*2;
            float w0 = Wz2[c0], w1 = Wz2[c0+1];
            float z0 = bz1[c0], z1 = bz1[c0+1];
            rs[mi*2+0] += tanhf(acc[mi][ni][0]+z0)*w0 + tanhf(acc[mi][ni][1]+z1)*w1;
            rs[mi*2+1] += tanhf(acc[mi][ni][2]+z0)*w0 + tanhf(acc[mi][ni][3]+z1)*w1;
        }
    #pragma unroll
    for (int r = 0; r < 4; r++){
        rs[r] += __shfl_xor_sync(0xffffffffu, rs[r], 1);
        rs[r] += __shfl_xor_sync(0xffffffffu, rs[r], 2);
    }
    if (lk == 0){
        int s0 = warp_m + lg;
        atomicAdd(&g_Glogit[bt*NS + s0     ], rs[0]);
        atomicAdd(&g_Glogit[bt*NS + s0 + 8 ], rs[1]);
        atomicAdd(&g_Glogit[bt*NS + s0 + 16], rs[2]);
        atomicAdd(&g_Glogit[bt*NS + s0 + 24], rs[3]);
    }
}

// ================= K3: FR/FW =================
__global__ void __launch_bounds__(256,2) k7_F(
        const float* __restrict__ br, const float* __restrict__ bw){
    extern __shared__ unsigned us[];
    uint32_t sbase = smem_u32(us);
    int tid = threadIdx.x, wid = tid >> 5, lane = tid & 31;
    int lg = lane >> 2, lk = lane & 3;
    int warp_m = (wid >> 1) * 32, warp_n = (wid & 1) * 64;
    int nt = blockIdx.x, bt = blockIdx.y, which = blockIdx.z;
    const unsigned* Wtf  = which ? g_Wtf : g_Wrtf;
    const float*    bsel = which ? bw : br;
    float* Out = which ? g_FW : g_FR;
    int c4v = (tid & 7) * 4, rb = tid >> 3;
    uint32_t swz16 = (uint32_t)(((tid & 7) ^ (rb & 7)) * 16);
    LDSM_OFFSETS();
    const unsigned* Ab = g_ftf + (size_t)bt*NS*HD;
    const unsigned* Bb = Wtf + (size_t)(nt*128)*HD;
    float acc[2][8][4]; ZERO_ACC(acc);

    const int NBLK = 32;
    GEMM_CP(0, 0, Ab, HD, Bb, HD);
    GEMM_CP(1, 1, Ab, HD, Bb, HD);
    int st = 0;
    for (int i = 0; i < NBLK; i++){
        CP_WAIT(1);
        __syncthreads();
        if (i + 2 < NBLK){
            int st2 = st + 2; if (st2 >= 3) st2 -= 3;
            GEMM_CP(i+2, st2, Ab, HD, Bb, HD);
        }
        compute32s(sbase + st*TILE_B, sbase + (3+st)*TILE_B, RA, RB, T, acc);
        if (++st == 3) st = 0;
    }

    #pragma unroll
    for (int mi = 0; mi < 2; mi++){
        int r0 = warp_m + mi*16 + lg;   // s index
        #pragma unroll
        for (int ni = 0; ni < 8; ni++){
            int h = nt*128 + warp_n + ni*8 + lk*2;
            float b0 = bsel[h], b1 = bsel[h+1];
            float2 v0 = make_float2(acc[mi][ni][0]+b0, acc[mi][ni][1]+b1);
            float2 v1 = make_float2(acc[mi][ni][2]+b0, acc[mi][ni][3]+b1);
            *reinterpret_cast<float2*>(Out + (size_t)r0*(NB*HD) + (size_t)bt*HD + h) = v0;
            *reinterpret_cast<float2*>(Out + (size_t)(r0+8)*(NB*HD) + (size_t)bt*HD + h) = v1;
        }
    }
}

// ---------------- K2: softmax ----------------
__global__ void k_softmax(){
    int bt = blockIdx.x, t = threadIdx.x;
    float v = g_Glogit[bt*NS + t];
    __shared__ float sm_[4], ss[4];
    float mx = v;
    #pragma unroll
    for (int o = 16; o; o >>= 1) mx = fmaxf(mx, __shfl_xor_sync(0xffffffffu, mx, o));
    if ((t & 31) == 0) sm_[t >> 5] = mx;
    __syncthreads();
    mx = fmaxf(fmaxf(sm_[0], sm_[1]), fmaxf(sm_[2], sm_[3]));
    float e = __expf(v - mx);
    float sum = e;
    #pragma unroll
    for (int o = 16; o; o >>= 1) sum += __shfl_xor_sync(0xffffffffu, sum, o);
    if ((t & 31) == 0) ss[t >> 5] = sum;
    __syncthreads();
    sum = ss[0] + ss[1] + ss[2] + ss[3];
    g_Gt[t*NB + bt] = e / sum;
}

// ---------------- K4: persistent scan (C in registers) ----------------
__device__ __forceinline__ void gsync(unsigned step, int tid, int cta){
    __syncthreads();
    if (tid == 0){
        __threadfence();
        stcg_u32(&g_flags[cta*32], step);
    }
    if (tid < NCTA_SCAN){
        while (ldcg_u32(&g_flags[tid*32]) < step) { }
    }
    __threadfence();
    __syncthreads();
}
__device__ __forceinline__ float gru_upd(float fr, float fw, float y1, float y2,
                                         float b_ur, float b_u, float c, float g){
    float r  = 1.f / (1.f + __expf(-(fr + y1 + b_ur)));
    float ht = tanhf(fw + r * (y2 + b_u));
    return g * ht + (1.f - g) * c;
}

__global__ void __launch_bounds__(256,1) k7_scan(
        const float* __restrict__ Ur, const float* __restrict__ bur,
        const float* __restrict__ U,  const float* __restrict__ bu){
    extern __shared__ unsigned us[];   // A subs: tiles 0-3; B resident: tiles 4-7
    uint32_t sbase = smem_u32(us);
    char* sc = reinterpret_cast<char*>(us);
    int cta = blockIdx.x, tid = threadIdx.x;
    int wid = tid >> 5, lane = tid & 31, lg = lane >> 2, lk = lane & 3;
    int warp_m = (wid >> 1) * 32, warp_n = (wid & 1) * 64;
    int c4v = (tid & 7) * 4, rb = tid >> 3;
    uint32_t swz16 = (uint32_t)(((tid & 7) ^ (rb & 7)) * 16);
    LDSM_OFFSETS();
    int nt = cta >> 3;
    int kcb = (cta & 7) * 128;
    const float* Wsel = (nt < 8) ? Ur : U;
    int nbase = (nt & 7) * 128;
    float* P = g_part + (size_t)cta * 16384;

    // resident tf32 weights in swizzled tiles 4..7
    #pragma unroll
    for (int j = 0; j < 16; j++){
        int s = j >> 2, n = rb + (j & 3)*32;
        float4 v = *reinterpret_cast<const float4*>(Wsel + (size_t)(nbase+n)*HD + kcb + s*32 + c4v);
        uint4 o = make_uint4(f2tf(v.x), f2tf(v.y), f2tf(v.z), f2tf(v.w));
        *reinterpret_cast<uint4*>(sc + (4+s)*TILE_B + n*128 + swz16) = o;
    }
    __syncthreads();

    int e  = (cta*256 + tid) * 4;
    int eb = e >> 10, eh = e & (HD-1);
    int nt1 = eh >> 7, hm = eh & 127;
    float4 vur = *reinterpret_cast<const float4*>(bur + eh);
    float4 vu  = *reinterpret_cast<const float4*>(bu + eh);
    float4 creg = make_float4(0.f, 0.f, 0.f, 0.f);   // own C elements, in registers

    unsigned bar = 0;
    for (int s = 0; s < NS; s++){
        float4 fr = *reinterpret_cast<const float4*>(g_FR + (size_t)s*NB*HD + (size_t)eb*HD + eh);
        float4 fw = *reinterpret_cast<const float4*>(g_FW + (size_t)s*NB*HD + (size_t)eb*HD + eh);
        float gg = g_Gt[s*NB + eb];

        #pragma unroll
        for (int sg = 0; sg < 4; sg++){
            #pragma unroll
            for (int j = 0; j < 4; j++){
                int r = rb + j*32;
                cpa16(sbase + sg*TILE_B + r*128 + swz16,
                      g_Ctf + (size_t)r*HD + kcb + sg*32 + c4v);
            }
            CP_COMMIT();
        }
        float acc[2][8][4]; ZERO_ACC(acc);
        #pragma unroll
        for (int sub = 0; sub < 4; sub++){
            if (sub == 0)      CP_WAIT(3);
            else if (sub == 1) CP_WAIT(2);
            else if (sub == 2) CP_WAIT(1);
            else               CP_WAIT(0);
            __syncthreads();
            compute32s(sbase + sub*TILE_B, sbase + (4+sub)*TILE_B, RA, RB, T, acc);
        }
        #pragma unroll
        for (int mi = 0; mi < 2; mi++){
            int r0 = warp_m + mi*16 + lg;
            #pragma unroll
            for (int ni = 0; ni < 8; ni++){
                int c = warp_n + ni*8 + lk*2;
                __stcg(reinterpret_cast<float2*>(P + r0*128 + c),
                       make_float2(acc[mi][ni][0], acc[mi][ni][1]));
                __stcg(reinterpret_cast<float2*>(P + (r0+8)*128 + c),
                       make_float2(acc[mi][ni][2], acc[mi][ni][3]));
            }
        }
        gsync(++bar, tid, cta);

        float4 y1 = make_float4(0,0,0,0), y2 = make_float4(0,0,0,0);
        #pragma unroll
        for (int kk = 0; kk < 8; kk++){
            float4 p1 = __ldcg(reinterpret_cast<const float4*>(
                g_part + (size_t)(nt1*8 + kk)*16384 + eb*128 + hm));
            float4 p2 = __ldcg(reinterpret_cast<const float4*>(
                g_part + (size_t)((nt1+8)*8 + kk)*16384 + eb*128 + hm));
            y1.x += p1.x; y1.y += p1.y; y1.z += p1.z; y1.w += p1.w;
            y2.x += p2.x; y2.y += p2.y; y2.z += p2.z; y2.w += p2.w;
        }
        creg.x = gru_upd(fr.x, fw.x, y1.x, y2.x, vur.x, vu.x, creg.x, gg);
        creg.y = gru_upd(fr.y, fw.y, y1.y, y2.y, vur.y, vu.y, creg.y, gg);
        creg.z = gru_upd(fr.z, fw.z, y1.z, y2.z, vur.z, vu.z, creg.z, gg);
        creg.w = gru_upd(fr.w, fw.w, y1.w, y2.w, vur.w, vu.w, creg.w, gg);
        uint4 ct;
        ct.x = f2tf(creg.x); ct.y = f2tf(creg.y); ct.z = f2tf(creg.z); ct.w = f2tf(creg.w);
        __stcg(reinterpret_cast<uint4*>(g_Ctf + (size_t)eb*HD + eh), ct);
        gsync(++bar, tid, cta);
    }
}

// ---------------- K5: final GEMM (pipelined split-K) ----------------
__global__ void __launch_bounds__(256,2) k7_out(){
    extern __shared__ unsigned us[];
    uint32_t sbase = smem_u32(us);
    int tid = threadIdx.x, wid = tid >> 5, lane = tid & 31;
    int lg = lane >> 2, lk = lane & 3;
    int warp_m = (wid >> 1) * 32, warp_n = (wid & 1) * 64;
    int nt = blockIdx.x, ks = blockIdx.y;   // ks in [0,12): seg = ks>>2
    int c4v = (tid & 7) * 4, rb = tid >> 3;
    uint32_t swz16 = (uint32_t)(((tid & 7) ^ (rb & 7)) * 16);
    LDSM_OFFSETS();
    int seg = ks >> 2;
    const unsigned* Ab = (seg == 0) ? g_pmtf : (seg == 1 ? g_Ctf : g_qtf);
    Ab += (ks & 3) * 256;
    const unsigned* Bb = g_Wmtf + (size_t)(nt*128)*(3*HD) + ks*256;
    float acc[2][8][4]; ZERO_ACC(acc);

    const int NBLK = 8;
    GEMM_CP(0, 0, Ab, HD, Bb, 3*HD);
    GEMM_CP(1, 1, Ab, HD, Bb, 3*HD);
    int st = 0;
    for (int i = 0; i < NBLK; i++){
        CP_WAIT(1);
        __syncthreads();
        if (i + 2 < NBLK){
            int st2 = st + 2; if (st2 >= 3) st2 -= 3;
            GEMM_CP(i+2, st2, Ab, HD, Bb, 3*HD);
        }
        compute32s(sbase + st*TILE_B, sbase + (3+st)*TILE_B, RA, RB, T, acc);
        if (++st == 3) st = 0;
    }
    #pragma unroll
    for (int mi = 0; mi < 2; mi++){
        int r0 = warp_m + mi*16 + lg;
        #pragma unroll
        for (int ni = 0; ni < 8; ni++){
            int h = nt*128 + warp_n + ni*8 + lk*2;
            atomicAdd(&g_Otmp[(size_t)r0*HD + h     ], acc[mi][ni][0]);
            atomicAdd(&g_Otmp[(size_t)r0*HD + h + 1 ], acc[mi][ni][1]);
            atomicAdd(&g_Otmp[(size_t)(r0+8)*HD + h    ], acc[mi][ni][2]);
            atomicAdd(&g_Otmp[(size_t)(r0+8)*HD + h + 1], acc[mi][ni][3]);
        }
    }
}

// ---------------- K6: bias + relu ----------------
__global__ void k_finish(const float* __restrict__ bm, float* __restrict__ out){
    int i = blockIdx.x * blockDim.x + threadIdx.x;
    if (i < NB*HD){
        float v = g_Otmp[i] + bm[i & (HD-1)];
        out[i] = fmaxf(v, 0.f);
    }
}

// ---------------- launch ----------------
extern "C" void kernel_launch(void* const* d_in, const int* in_sizes, int n_in,
                              void* d_out, int out_size){
    (void)in_sizes; (void)n_in; (void)out_size;
    const float* facts     = (const float*)d_in[0];
    const float* questions = (const float*)d_in[1];
    const float* prevM     = (const float*)d_in[2];
    const float* Wr  = (const float*)d_in[3];
    const float* br  = (const float*)d_in[4];
    const float* Ur  = (const float*)d_in[5];
    const float* bur = (const float*)d_in[6];
    const float* W   = (const float*)d_in[7];
    const float* bw  = (const float*)d_in[8];
    const float* U   = (const float*)d_in[9];
    const float* bu  = (const float*)d_in[10];
    const float* Wz1 = (const float*)d_in[11];
    const float* bz1 = (const float*)d_in[12];
    const float* Wz2 = (const float*)d_in[13];
    // d_in[14] = bz2: softmax shift-invariant, cancels.
    const float* Wm  = (const float*)d_in[15];
    const float* bm  = (const float*)d_in[16];
    float* out = (float*)d_out;

    static int attr_done = 0;
    if (!attr_done){
        cudaFuncSetAttribute(k7_G,    cudaFuncAttributeMaxDynamicSharedMemorySize, GEMM_SMEM);
        cudaFuncSetAttribute(k7_F,    cudaFuncAttributeMaxDynamicSharedMemorySize, GEMM_SMEM);
        cudaFuncSetAttribute(k7_scan, cudaFuncAttributeMaxDynamicSharedMemorySize, SCAN_SMEM);
        cudaFuncSetAttribute(k7_out,  cudaFuncAttributeMaxDynamicSharedMemorySize, GEMM_SMEM);
        attr_done = 1;
    }

    unsigned* dWz1tf; cudaGetSymbolAddress((void**)&dWz1tf, g_Wz1tf);
    unsigned* dWrtf;  cudaGetSymbolAddress((void**)&dWrtf,  g_Wrtf);
    unsigned* dWtf;   cudaGetSymbolAddress((void**)&dWtf,   g_Wtf);
    unsigned* dftf;   cudaGetSymbolAddress((void**)&dftf,   g_ftf);
    unsigned* dWmtf;  cudaGetSymbolAddress((void**)&dWmtf,  g_Wmtf);
    unsigned* dpmtf;  cudaGetSymbolAddress((void**)&dpmtf,  g_pmtf);
    unsigned* dqtf;   cudaGetSymbolAddress((void**)&dqtf,   g_qtf);

    k_init<<<512, 256>>>();
    k_cvt<<<2048, 256>>>((const float4*)facts, (uint4*)dftf,   (NB*NS*HD)/4);
    k_cvt<<<1024, 256>>>((const float4*)Wz1,   (uint4*)dWz1tf, (HD*4*HD)/4);
    k_cvt<<<512, 256>>>((const float4*)Wr,     (uint4*)dWrtf,  (HD*HD)/4);
    k_cvt<<<512, 256>>>((const float4*)W,      (uint4*)dWtf,   (HD*HD)/4);
    k_cvt<<<1024, 256>>>((const float4*)Wm,    (uint4*)dWmtf,  (HD*3*HD)/4);
    k_cvt<<<128, 256>>>((const float4*)prevM,  (uint4*)dpmtf,  (NB*HD)/4);
    k_cvt<<<128, 256>>>((const float4*)questions, (uint4*)dqtf, (NB*HD)/4);
    k_zb<<<NROW, 256>>>(facts, questions, prevM);
    dim3 gG(8, 128);
    k7_G<<<gG, 256, GEMM_SMEM>>>(bz1, Wz2);
    k_softmax<<<128, 128>>>();
    dim3 gF(8, 128, 2);
    k7_F<<<gF, 256, GEMM_SMEM>>>(br, bw);
    k7_scan<<<NCTA_SCAN, 256, SCAN_SMEM>>>(Ur, bur, U, bu);
    dim3 gO(8, 12);
    k7_out<<<gO, 256, GEMM_SMEM>>>();
    k_finish<<<512, 256>>>(bm, out);
}

// round 10
// speedup vs baseline: 1.7261x; 1.5963x over previous
#include <cuda_runtime.h>
#include <cuda_fp16.h>
#include <cstdint>
#include <cstddef>

#define HD 1024
#define NB 128
#define NS 128
#define NROW (NB*NS)
#define NCTA_SCAN 128
#define TILE_B 16384            // 128 rows x 64 fp16 (128B/row), swizzled
#define GEMM_SMEM (6*TILE_B)    // 98304: 3xA + 3xB (2 CTAs/SM)
#define SCAN_SMEM (4*TILE_B)    // 65536: 2xA + 2xB resident

// ---------------- scratch ----------------
__device__ __align__(16) float g_FR[(size_t)NS*NB*HD];
__device__ __align__(16) float g_FW[(size_t)NS*NB*HD];
__device__ __align__(16) unsigned g_Ch[NB*HD/2];          // fp16 C state (half2 packed)
__device__ __align__(16) float g_Otmp[NB*HD];
__device__ __align__(16) float g_part[(size_t)NCTA_SCAN*128*128];
__device__ __align__(16) float g_Glogit[NROW];
__device__ __align__(16) float g_Gt[NS*NB];
// pre-converted fp16 operands (half2 packed in unsigned)
__device__ __align__(16) unsigned g_fh[(size_t)NB*NS*HD/2];
__device__ __align__(16) unsigned g_zh[(size_t)NROW*4*HD/2];
__device__ __align__(16) unsigned g_Wz1h[(size_t)HD*4*HD/2];
__device__ __align__(16) unsigned g_Wrh[(size_t)HD*HD/2];
__device__ __align__(16) unsigned g_Wh[(size_t)HD*HD/2];
__device__ __align__(16) unsigned g_Urh[(size_t)HD*HD/2];   // recurrent weights (THE FIX)
__device__ __align__(16) unsigned g_Uh[(size_t)HD*HD/2];
__device__ __align__(16) unsigned g_Wmh[(size_t)HD*3*HD/2];
__device__ __align__(16) unsigned g_pmh[NB*HD/2];
__device__ __align__(16) unsigned g_qh[NB*HD/2];
__device__ __align__(16) unsigned g_flags[NCTA_SCAN*32];

// ---------------- helpers ----------------
__device__ __forceinline__ unsigned pack_h2(float x, float y){
    __half2 h = __floats2half2_rn(x, y);
    return *reinterpret_cast<unsigned*>(&h);
}
__device__ __forceinline__ uint32_t smem_u32(const void* p){
    uint32_t a; asm("{ .reg .u64 t; cvta.to.shared.u64 t, %1; cvt.u32.u64 %0, t; }"
                    : "=r"(a) : "l"(p)); return a;
}
__device__ __forceinline__ void cpa16(uint32_t dst, const void* src){
    asm volatile("cp.async.cg.shared.global [%0], [%1], 16;" :: "r"(dst), "l"(src));
}
#define CP_COMMIT() asm volatile("cp.async.commit_group;" ::: "memory")
#define CP_WAIT(n)  asm volatile("cp.async.wait_group %0;" :: "n"(n) : "memory")

__device__ __forceinline__ unsigned ldcg_u32(const unsigned* p){
    unsigned v; asm volatile("ld.global.cg.u32 %0, [%1];" : "=r"(v) : "l"(p)); return v;
}
__device__ __forceinline__ void stcg_u32(unsigned* p, unsigned v){
    asm volatile("st.global.cg.u32 [%0], %1;" :: "l"(p), "r"(v) : "memory");
}
__device__ __forceinline__ void ldsm4(unsigned* r, uint32_t addr){
    asm volatile("ldmatrix.sync.aligned.m8n8.x4.shared.b16 {%0,%1,%2,%3}, [%4];"
        : "=r"(r[0]),"=r"(r[1]),"=r"(r[2]),"=r"(r[3]) : "r"(addr));
}
__device__ __forceinline__ void mma16(float* d, const unsigned* a, const unsigned* b){
    asm volatile("mma.sync.aligned.m16n8k16.row.col.f32.f16.f16.f32 "
        "{%0,%1,%2,%3},{%4,%5,%6,%7},{%8,%9},{%0,%1,%2,%3};\n"
        : "+f"(d[0]),"+f"(d[1]),"+f"(d[2]),"+f"(d[3])
        : "r"(a[0]),"r"(a[1]),"r"(a[2]),"r"(a[3]),"r"(b[0]),"r"(b[1]));
}

// 128x128x64 (fp16) tile-step via ldmatrix. 4 k-steps of 16.
__device__ __forceinline__ void compute64h(uint32_t aBase, uint32_t bBase,
        const uint32_t* RA, const uint32_t* RB, const uint32_t* TA, const uint32_t* TB,
        float acc[2][8][4]){
    #pragma unroll
    for (int ks = 0; ks < 4; ks++){
        unsigned a0[4], a1[4], bb[4][4];
        ldsm4(a0, aBase + RA[0] + TA[ks]);
        ldsm4(a1, aBase + RA[1] + TA[ks]);
        #pragma unroll
        for (int p = 0; p < 4; p++) ldsm4(bb[p], bBase + RB[p] + TB[ks]);
        #pragma unroll
        for (int mi = 0; mi < 2; mi++){
            const unsigned* a = mi ? a1 : a0;
            #pragma unroll
            for (int p = 0; p < 4; p++){
                unsigned bl[2] = {bb[p][0], bb[p][1]};
                unsigned bh[2] = {bb[p][2], bb[p][3]};
                mma16(acc[mi][2*p],   a, bl);
                mma16(acc[mi][2*p+1], a, bh);
            }
        }
    }
}

// fp16 ldmatrix offsets (bytes).
#define LDSM_OFFSETS_H() \
    int rowA = warp_m + (lane & 15); \
    uint32_t RA[2] = { (uint32_t)rowA*128u, (uint32_t)(rowA+16)*128u }; \
    uint32_t RB[4]; \
    _Pragma("unroll") for (int p_ = 0; p_ < 4; p_++) \
        RB[p_] = (uint32_t)(warp_n + p_*16 + (lane & 7) + ((lane >> 4) & 1)*8)*128u; \
    uint32_t TA[4], TB[4]; \
    _Pragma("unroll") for (int k_ = 0; k_ < 4; k_++){ \
        TA[k_] = (uint32_t)(((k_*2 + (lane >> 4)) ^ (rowA & 7))*16); \
        TB[k_] = (uint32_t)(((k_*2 + ((lane >> 3) & 1)) ^ (lane & 7))*16); }

#define ZERO_ACC(acc) { \
    _Pragma("unroll") for (int _i=0;_i<2;_i++) \
    _Pragma("unroll") for (int _j=0;_j<8;_j++) \
    _Pragma("unroll") for (int _k=0;_k<4;_k++) acc[_i][_j][_k]=0.f; }

// 256-thread fp16 loader: A 128 rows + B 128 rows, 64 K (128 bytes) per block
#define GEMM_CPH(i_, st_, Ab_, AldB_, Bb_, BldB_) { \
    size_t kb_ = (size_t)(i_)*128; \
    _Pragma("unroll") for (int j = 0; j < 4; j++){ int r_ = rb + j*32; \
        cpa16(sbase + (st_)*TILE_B + r_*128 + swz16, \
              (Ab_) + (size_t)r_*(AldB_) + kb_ + u16); \
        cpa16(sbase + (3 + (st_))*TILE_B + r_*128 + swz16, \
              (Bb_) + (size_t)r_*(BldB_) + kb_ + u16); } CP_COMMIT(); }

// ---------------- K0: per-replay init ----------------
__global__ void k_init(){
    int i = blockIdx.x * blockDim.x + threadIdx.x;
    if (i < NCTA_SCAN*32) g_flags[i] = 0u;
    if (i < NROW) g_Glogit[i] = 0.f;
    if (i < NB*HD/2) g_Ch[i] = 0u;
    if (i < NB*HD) g_Otmp[i] = 0.f;
}

// ---------------- Kc: fp32 -> fp16 bulk convert ----------------
__global__ void k_cvt_h(const float4* __restrict__ src, uint2* __restrict__ dst, int n4){
    for (int i = blockIdx.x*blockDim.x + threadIdx.x; i < n4; i += gridDim.x*blockDim.x){
        float4 v = src[i];
        dst[i] = make_uint2(pack_h2(v.x, v.y), pack_h2(v.z, v.w));
    }
}

// ---------------- Kz: build z (fp16) ----------------
__global__ void k_zb_h(const float* __restrict__ facts, const float* __restrict__ q,
                       const float* __restrict__ pm){
    int row = blockIdx.x;           // bt*NS + s
    int bt = row >> 7;
    int t = threadIdx.x;
    float4 f  = *reinterpret_cast<const float4*>(facts + (size_t)row*HD + t*4);
    float4 qv = *reinterpret_cast<const float4*>(q  + (size_t)bt*HD + t*4);
    float4 mv = *reinterpret_cast<const float4*>(pm + (size_t)bt*HD + t*4);
    char* zr = reinterpret_cast<char*>(g_zh) + (size_t)row*8192;  // 4*HD fp16
    *reinterpret_cast<uint2*>(zr + 0*2048 + t*8) =
        make_uint2(pack_h2(f.x*qv.x, f.y*qv.y), pack_h2(f.z*qv.z, f.w*qv.w));
    *reinterpret_cast<uint2*>(zr + 1*2048 + t*8) =
        make_uint2(pack_h2(f.x*mv.x, f.y*mv.y), pack_h2(f.z*mv.z, f.w*mv.w));
    *reinterpret_cast<uint2*>(zr + 2*2048 + t*8) =
        make_uint2(pack_h2(fabsf(f.x-qv.x), fabsf(f.y-qv.y)), pack_h2(fabsf(f.z-qv.z), fabsf(f.w-qv.w)));
    *reinterpret_cast<uint2*>(zr + 3*2048 + t*8) =
        make_uint2(pack_h2(fabsf(f.x-mv.x), fabsf(f.y-mv.y)), pack_h2(fabsf(f.z-mv.z), fabsf(f.w-mv.w)));
}

// ================= K1: G logits =================
__global__ void __launch_bounds__(256,2) k9_G(
        const float* __restrict__ bz1, const float* __restrict__ Wz2){
    extern __shared__ unsigned us[];
    uint32_t sbase = smem_u32(us);
    int tid = threadIdx.x, wid = tid >> 5, lane = tid & 31;
    int lg = lane >> 2, lk = lane & 3;
    int warp_m = (wid >> 1) * 32, warp_n = (wid & 1) * 64;
    int nt = blockIdx.x, bt = blockIdx.y;
    int u16 = (tid & 7) * 16, rb = tid >> 3;
    uint32_t swz16 = (uint32_t)(((tid & 7) ^ (rb & 7)) * 16);
    LDSM_OFFSETS_H();
    const char* Ab = reinterpret_cast<const char*>(g_zh) + (size_t)bt*NS*8192;
    const char* Bb = reinterpret_cast<const char*>(g_Wz1h) + (size_t)(nt*128)*8192;
    float acc[2][8][4]; ZERO_ACC(acc);

    const int NBLK = 64;   // 64 K per block
    GEMM_CPH(0, 0, Ab, 8192, Bb, 8192);
    GEMM_CPH(1, 1, Ab, 8192, Bb, 8192);
    int st = 0;
    for (int i = 0; i < NBLK; i++){
        CP_WAIT(1);
        __syncthreads();
        if (i + 2 < NBLK){
            int st2 = st + 2; if (st2 >= 3) st2 -= 3;
            GEMM_CPH(i+2, st2, Ab, 8192, Bb, 8192);
        }
        compute64h(sbase + st*TILE_B, sbase + (3+st)*TILE_B, RA, RB, TA, TB, acc);
        if (++st == 3) st = 0;
    }

    float rs[4] = {0.f, 0.f, 0.f, 0.f};
    #pragma unroll
    for (int mi = 0; mi < 2; mi++)
        #pragma unroll
        for (int ni = 0; ni < 8; ni++){
            int c0 = nt*128 + warp_n + ni*8 + lk*2;
            float w0 = Wz2[c0], w1 = Wz2[c0+1];
            float z0 = bz1[c0], z1 = bz1[c0+1];
            rs[mi*2+0] += tanhf(acc[mi][ni][0]+z0)*w0 + tanhf(acc[mi][ni][1]+z1)*w1;
            rs[mi*2+1] += tanhf(acc[mi][ni][2]+z0)*w0 + tanhf(acc[mi][ni][3]+z1)*w1;
        }
    #pragma unroll
    for (int r = 0; r < 4; r++){
        rs[r] += __shfl_xor_sync(0xffffffffu, rs[r], 1);
        rs[r] += __shfl_xor_sync(0xffffffffu, rs[r], 2);
    }
    if (lk == 0){
        int s0 = warp_m + lg;
        atomicAdd(&g_Glogit[bt*NS + s0     ], rs[0]);
        atomicAdd(&g_Glogit[bt*NS + s0 + 8 ], rs[1]);
        atomicAdd(&g_Glogit[bt*NS + s0 + 16], rs[2]);
        atomicAdd(&g_Glogit[bt*NS + s0 + 24], rs[3]);
    }
}

// ================= K3: FR/FW =================
__global__ void __launch_bounds__(256,2) k9_F(
        const float* __restrict__ br, const float* __restrict__ bw){
    extern __shared__ unsigned us[];
    uint32_t sbase = smem_u32(us);
    int tid = threadIdx.x, wid = tid >> 5, lane = tid & 31;
    int lg = lane >> 2, lk = lane & 3;
    int warp_m = (wid >> 1) * 32, warp_n = (wid & 1) * 64;
    int nt = blockIdx.x, bt = blockIdx.y, which = blockIdx.z;
    const unsigned* Wsel = which ? g_Wh : g_Wrh;
    const float*    bsel = which ? bw : br;
    float* Out = which ? g_FW : g_FR;
    int u16 = (tid & 7) * 16, rb = tid >> 3;
    uint32_t swz16 = (uint32_t)(((tid & 7) ^ (rb & 7)) * 16);
    LDSM_OFFSETS_H();
    const char* Ab = reinterpret_cast<const char*>(g_fh) + (size_t)bt*NS*2048;
    const char* Bb = reinterpret_cast<const char*>(Wsel) + (size_t)(nt*128)*2048;
    float acc[2][8][4]; ZERO_ACC(acc);

    const int NBLK = 16;
    GEMM_CPH(0, 0, Ab, 2048, Bb, 2048);
    GEMM_CPH(1, 1, Ab, 2048, Bb, 2048);
    int st = 0;
    for (int i = 0; i < NBLK; i++){
        CP_WAIT(1);
        __syncthreads();
        if (i + 2 < NBLK){
            int st2 = st + 2; if (st2 >= 3) st2 -= 3;
            GEMM_CPH(i+2, st2, Ab, 2048, Bb, 2048);
        }
        compute64h(sbase + st*TILE_B, sbase + (3+st)*TILE_B, RA, RB, TA, TB, acc);
        if (++st == 3) st = 0;
    }

    #pragma unroll
    for (int mi = 0; mi < 2; mi++){
        int r0 = warp_m + mi*16 + lg;   // s index
        #pragma unroll
        for (int ni = 0; ni < 8; ni++){
            int h = nt*128 + warp_n + ni*8 + lk*2;
            float b0 = bsel[h], b1 = bsel[h+1];
            float2 v0 = make_float2(acc[mi][ni][0]+b0, acc[mi][ni][1]+b1);
            float2 v1 = make_float2(acc[mi][ni][2]+b0, acc[mi][ni][3]+b1);
            *reinterpret_cast<float2*>(Out + (size_t)r0*(NB*HD) + (size_t)bt*HD + h) = v0;
            *reinterpret_cast<float2*>(Out + (size_t)(r0+8)*(NB*HD) + (size_t)bt*HD + h) = v1;
        }
    }
}

// ---------------- K2: softmax ----------------
__global__ void k_softmax(){
    int bt = blockIdx.x, t = threadIdx.x;
    float v = g_Glogit[bt*NS + t];
    __shared__ float sm_[4], ss[4];
    float mx = v;
    #pragma unroll
    for (int o = 16; o; o >>= 1) mx = fmaxf(mx, __shfl_xor_sync(0xffffffffu, mx, o));
    if ((t & 31) == 0) sm_[t >> 5] = mx;
    __syncthreads();
    mx = fmaxf(fmaxf(sm_[0], sm_[1]), fmaxf(sm_[2], sm_[3]));
    float e = __expf(v - mx);
    float sum = e;
    #pragma unroll
    for (int o = 16; o; o >>= 1) sum += __shfl_xor_sync(0xffffffffu, sum, o);
    if ((t & 31) == 0) ss[t >> 5] = sum;
    __syncthreads();
    sum = ss[0] + ss[1] + ss[2] + ss[3];
    g_Gt[t*NB + bt] = e / sum;
}

// ---------------- K4: persistent scan (fp16 GEMM with Ur/U, C in registers) ----------------
__device__ __forceinline__ void gsync(unsigned step, int tid, int cta){
    __syncthreads();
    if (tid == 0){
        __threadfence();
        stcg_u32(&g_flags[cta*32], step);
    }
    if (tid < NCTA_SCAN){
        while (ldcg_u32(&g_flags[tid*32]) < step) { }
    }
    __threadfence();
    __syncthreads();
}
__device__ __forceinline__ float gru_upd(float fr, float fw, float y1, float y2,
                                         float b_ur, float b_u, float c, float g){
    float r  = 1.f / (1.f + __expf(-(fr + y1 + b_ur)));
    float ht = tanhf(fw + r * (y2 + b_u));
    return g * ht + (1.f - g) * c;
}

__global__ void __launch_bounds__(256,1) k9_scan(
        const float* __restrict__ bur, const float* __restrict__ bu){
    extern __shared__ unsigned us[];   // A subs: tiles 0-1; B resident: tiles 2-3
    uint32_t sbase = smem_u32(us);
    int cta = blockIdx.x, tid = threadIdx.x;
    int wid = tid >> 5, lane = tid & 31, lg = lane >> 2, lk = lane & 3;
    int warp_m = (wid >> 1) * 32, warp_n = (wid & 1) * 64;
    int u16 = (tid & 7) * 16, rb = tid >> 3;
    uint32_t swz16 = (uint32_t)(((tid & 7) ^ (rb & 7)) * 16);
    LDSM_OFFSETS_H();
    int nt = cta >> 3;
    int kcb = (cta & 7) * 128;      // K slice (fp16 elems)
    const unsigned* Wsel = (nt < 8) ? g_Urh : g_Uh;    // RECURRENT weights (fixed)
    int nbase = (nt & 7) * 128;
    float* P = g_part + (size_t)cta * 16384;
    const char* Wb = reinterpret_cast<const char*>(Wsel) + (size_t)nbase*2048 + kcb*2;
    const char* Cb = reinterpret_cast<const char*>(g_Ch) + kcb*2;

    // resident fp16 weights in tiles 2,3 (k 0-63, 64-127 of slice)
    #pragma unroll
    for (int t2 = 0; t2 < 2; t2++){
        #pragma unroll
        for (int j = 0; j < 4; j++){
            int r = rb + j*32;
            cpa16(sbase + (2+t2)*TILE_B + r*128 + swz16,
                  Wb + (size_t)r*2048 + t2*128 + u16);
        }
    }
    CP_COMMIT();
    CP_WAIT(0);
    __syncthreads();

    int e  = (cta*256 + tid) * 4;
    int eb = e >> 10, eh = e & (HD-1);
    int nt1 = eh >> 7, hm = eh & 127;
    float4 vur = *reinterpret_cast<const float4*>(bur + eh);
    float4 vu  = *reinterpret_cast<const float4*>(bu + eh);
    float4 creg = make_float4(0.f, 0.f, 0.f, 0.f);

    unsigned bar = 0;
    for (int s = 0; s < NS; s++){
        float4 fr = *reinterpret_cast<const float4*>(g_FR + (size_t)s*NB*HD + (size_t)eb*HD + eh);
        float4 fw = *reinterpret_cast<const float4*>(g_FW + (size_t)s*NB*HD + (size_t)eb*HD + eh);
        float gg = g_Gt[s*NB + eb];

        // phase A: C slice (fp16), 2 sub-tiles of 64K
        #pragma unroll
        for (int sg = 0; sg < 2; sg++){
            #pragma unroll
            for (int j = 0; j < 4; j++){
                int r = rb + j*32;
                cpa16(sbase + sg*TILE_B + r*128 + swz16,
                      Cb + (size_t)r*2048 + sg*128 + u16);
            }
            CP_COMMIT();
        }
        float acc[2][8][4]; ZERO_ACC(acc);
        CP_WAIT(1);
        __syncthreads();
        compute64h(sbase + 0*TILE_B, sbase + 2*TILE_B, RA, RB, TA, TB, acc);
        CP_WAIT(0);
        __syncthreads();
        compute64h(sbase + 1*TILE_B, sbase + 3*TILE_B, RA, RB, TA, TB, acc);

        #pragma unroll
        for (int mi = 0; mi < 2; mi++){
            int r0 = warp_m + mi*16 + lg;
            #pragma unroll
            for (int ni = 0; ni < 8; ni++){
                int c = warp_n + ni*8 + lk*2;
                __stcg(reinterpret_cast<float2*>(P + r0*128 + c),
                       make_float2(acc[mi][ni][0], acc[mi][ni][1]));
                __stcg(reinterpret_cast<float2*>(P + (r0+8)*128 + c),
                       make_float2(acc[mi][ni][2], acc[mi][ni][3]));
            }
        }
        gsync(++bar, tid, cta);

        float4 y1 = make_float4(0,0,0,0), y2 = make_float4(0,0,0,0);
        #pragma unroll
        for (int kk = 0; kk < 8; kk++){
            float4 p1 = __ldcg(reinterpret_cast<const float4*>(
                g_part + (size_t)(nt1*8 + kk)*16384 + eb*128 + hm));
            float4 p2 = __ldcg(reinterpret_cast<const float4*>(
                g_part + (size_t)((nt1+8)*8 + kk)*16384 + eb*128 + hm));
            y1.x += p1.x; y1.y += p1.y; y1.z += p1.z; y1.w += p1.w;
            y2.x += p2.x; y2.y += p2.y; y2.z += p2.z; y2.w += p2.w;
        }
        creg.x = gru_upd(fr.x, fw.x, y1.x, y2.x, vur.x, vu.x, creg.x, gg);
        creg.y = gru_upd(fr.y, fw.y, y1.y, y2.y, vur.y, vu.y, creg.y, gg);
        creg.z = gru_upd(fr.z, fw.z, y1.z, y2.z, vur.z, vu.z, creg.z, gg);
        creg.w = gru_upd(fr.w, fw.w, y1.w, y2.w, vur.w, vu.w, creg.w, gg);
        __stcg(reinterpret_cast<uint2*>(g_Ch + (e >> 1)),
               make_uint2(pack_h2(creg.x, creg.y), pack_h2(creg.z, creg.w)));
        gsync(++bar, tid, cta);
    }
}

// ---------------- K5: final GEMM (pipelined split-K) ----------------
__global__ void __launch_bounds__(256,2) k9_out(){
    extern __shared__ unsigned us[];
    uint32_t sbase = smem_u32(us);
    int tid = threadIdx.x, wid = tid >> 5, lane = tid & 31;
    int lg = lane >> 2, lk = lane & 3;
    int warp_m = (wid >> 1) * 32, warp_n = (wid & 1) * 64;
    int nt = blockIdx.x, ks = blockIdx.y;   // ks in [0,12)
    int u16 = (tid & 7) * 16, rb = tid >> 3;
    uint32_t swz16 = (uint32_t)(((tid & 7) ^ (rb & 7)) * 16);
    LDSM_OFFSETS_H();
    int seg = ks >> 2;
    const unsigned* Asel = (seg == 0) ? g_pmh : (seg == 1 ? g_Ch : g_qh);
    const char* Ab = reinterpret_cast<const char*>(Asel) + (ks & 3) * 512;  // 256 fp16
    const char* Bb = reinterpret_cast<const char*>(g_Wmh) + (size_t)(nt*128)*6144 + ks*512;
    float acc[2][8][4]; ZERO_ACC(acc);

    const int NBLK = 4;
    GEMM_CPH(0, 0, Ab, 2048, Bb, 6144);
    GEMM_CPH(1, 1, Ab, 2048, Bb, 6144);
    int st = 0;
    for (int i = 0; i < NBLK; i++){
        CP_WAIT(1);
        __syncthreads();
        if (i + 2 < NBLK){
            int st2 = st + 2; if (st2 >= 3) st2 -= 3;
            GEMM_CPH(i+2, st2, Ab, 2048, Bb, 6144);
        }
        compute64h(sbase + st*TILE_B, sbase + (3+st)*TILE_B, RA, RB, TA, TB, acc);
        if (++st == 3) st = 0;
    }
    #pragma unroll
    for (int mi = 0; mi < 2; mi++){
        int r0 = warp_m + mi*16 + lg;
        #pragma unroll
        for (int ni = 0; ni < 8; ni++){
            int h = nt*128 + warp_n + ni*8 + lk*2;
            atomicAdd(&g_Otmp[(size_t)r0*HD + h     ], acc[mi][ni][0]);
            atomicAdd(&g_Otmp[(size_t)r0*HD + h + 1 ], acc[mi][ni][1]);
            atomicAdd(&g_Otmp[(size_t)(r0+8)*HD + h    ], acc[mi][ni][2]);
            atomicAdd(&g_Otmp[(size_t)(r0+8)*HD + h + 1], acc[mi][ni][3]);
        }
    }
}

// ---------------- K6: bias + relu ----------------
__global__ void k_finish(const float* __restrict__ bm, float* __restrict__ out){
    int i = blockIdx.x * blockDim.x + threadIdx.x;
    if (i < NB*HD){
        float v = g_Otmp[i] + bm[i & (HD-1)];
        out[i] = fmaxf(v, 0.f);
    }
}

// ---------------- launch ----------------
extern "C" void kernel_launch(void* const* d_in, const int* in_sizes, int n_in,
                              void* d_out, int out_size){
    (void)in_sizes; (void)n_in; (void)out_size;
    const float* facts     = (const float*)d_in[0];
    const float* questions = (const float*)d_in[1];
    const float* prevM     = (const float*)d_in[2];
    const float* Wr  = (const float*)d_in[3];
    const float* br  = (const float*)d_in[4];
    const float* Ur  = (const float*)d_in[5];
    const float* bur = (const float*)d_in[6];
    const float* W   = (const float*)d_in[7];
    const float* bw  = (const float*)d_in[8];
    const float* U   = (const float*)d_in[9];
    const float* bu  = (const float*)d_in[10];
    const float* Wz1 = (const float*)d_in[11];
    const float* bz1 = (const float*)d_in[12];
    const float* Wz2 = (const float*)d_in[13];
    // d_in[14] = bz2: softmax shift-invariant, cancels.
    const float* Wm  = (const float*)d_in[15];
    const float* bm  = (const float*)d_in[16];
    float* out = (float*)d_out;

    static int attr_done = 0;
    if (!attr_done){
        cudaFuncSetAttribute(k9_G,    cudaFuncAttributeMaxDynamicSharedMemorySize, GEMM_SMEM);
        cudaFuncSetAttribute(k9_F,    cudaFuncAttributeMaxDynamicSharedMemorySize, GEMM_SMEM);
        cudaFuncSetAttribute(k9_scan, cudaFuncAttributeMaxDynamicSharedMemorySize, SCAN_SMEM);
        cudaFuncSetAttribute(k9_out,  cudaFuncAttributeMaxDynamicSharedMemorySize, GEMM_SMEM);
        attr_done = 1;
    }

    unsigned *dWz1h, *dWrh, *dWh, *dUrh, *dUh, *dfh, *dWmh, *dpmh, *dqh;
    cudaGetSymbolAddress((void**)&dWz1h, g_Wz1h);
    cudaGetSymbolAddress((void**)&dWrh,  g_Wrh);
    cudaGetSymbolAddress((void**)&dWh,   g_Wh);
    cudaGetSymbolAddress((void**)&dUrh,  g_Urh);
    cudaGetSymbolAddress((void**)&dUh,   g_Uh);
    cudaGetSymbolAddress((void**)&dfh,   g_fh);
    cudaGetSymbolAddress((void**)&dWmh,  g_Wmh);
    cudaGetSymbolAddress((void**)&dpmh,  g_pmh);
    cudaGetSymbolAddress((void**)&dqh,   g_qh);

    k_init<<<512, 256>>>();
    k_cvt_h<<<2048, 256>>>((const float4*)facts, (uint2*)dfh,   (NB*NS*HD)/4);
    k_cvt_h<<<1024, 256>>>((const float4*)Wz1,   (uint2*)dWz1h, (HD*4*HD)/4);
    k_cvt_h<<<512, 256>>>((const float4*)Wr,     (uint2*)dWrh,  (HD*HD)/4);
    k_cvt_h<<<512, 256>>>((const float4*)W,      (uint2*)dWh,   (HD*HD)/4);
    k_cvt_h<<<512, 256>>>((const float4*)Ur,     (uint2*)dUrh,  (HD*HD)/4);
    k_cvt_h<<<512, 256>>>((const float4*)U,      (uint2*)dUh,   (HD*HD)/4);
    k_cvt_h<<<1024, 256>>>((const float4*)Wm,    (uint2*)dWmh,  (HD*3*HD)/4);
    k_cvt_h<<<128, 256>>>((const float4*)prevM,  (uint2*)dpmh,  (NB*HD)/4);
    k_cvt_h<<<128, 256>>>((const float4*)questions, (uint2*)dqh, (NB*HD)/4);
    k_zb_h<<<NROW, 256>>>(facts, questions, prevM);
    dim3 gG(8, 128);
    k9_G<<<gG, 256, GEMM_SMEM>>>(bz1, Wz2);
    k_softmax<<<128, 128>>>();
    dim3 gF(8, 128, 2);
    k9_F<<<gF, 256, GEMM_SMEM>>>(br, bw);
    k9_scan<<<NCTA_SCAN, 256, SCAN_SMEM>>>(bur, bu);
    dim3 gO(8, 12);
    k9_out<<<gO, 256, GEMM_SMEM>>>();
    k_finish<<<512, 256>>>(bm, out);
}

// round 11
// speedup vs baseline: 1.7919x; 1.0381x over previous
#include <cuda_runtime.h>
#include <cuda_fp16.h>
#include <cstdint>
#include <cstddef>

#define HD 1024
#define NB 128
#define NS 128
#define NROW (NB*NS)
#define NCTA_SCAN 128
#define TILE_B 16384            // 128 rows x 64 fp16 (128B/row), swizzled
#define TILE_S 8192             // 64 rows x 64 fp16 (128B/row), swizzled (scan B)
#define GEMM_SMEM (6*TILE_B)    // 98304: 3xA + 3xB (2 CTAs/SM)
#define SCAN_SMEM (4*TILE_B + 4*TILE_S)  // 98304: 4 A subs + 4 B resident chunks

// ---------------- scratch ----------------
__device__ __align__(16) unsigned g_FRh[(size_t)NS*NB*HD/2];   // fp16 [s][b][h]
__device__ __align__(16) unsigned g_FWh[(size_t)NS*NB*HD/2];
__device__ __align__(16) unsigned g_Ch[NB*HD/2];               // fp16 C state
__device__ __align__(16) float g_Otmp[NB*HD];
__device__ __align__(16) unsigned g_parth[(size_t)NCTA_SCAN*128*32]; // fp16 partials: 128x64 per CTA
__device__ __align__(16) float g_Glogit[NROW];
__device__ __align__(16) float g_Gt[NS*NB];
// pre-converted fp16 operands (half2 packed in unsigned)
__device__ __align__(16) unsigned g_fh[(size_t)NB*NS*HD/2];
__device__ __align__(16) unsigned g_zh[(size_t)NROW*4*HD/2];
__device__ __align__(16) unsigned g_Wz1h[(size_t)HD*4*HD/2];
__device__ __align__(16) unsigned g_Wrh[(size_t)HD*HD/2];
__device__ __align__(16) unsigned g_Wh[(size_t)HD*HD/2];
__device__ __align__(16) unsigned g_Urh[(size_t)HD*HD/2];
__device__ __align__(16) unsigned g_Uh[(size_t)HD*HD/2];
__device__ __align__(16) unsigned g_Wmh[(size_t)HD*3*HD/2];
__device__ __align__(16) unsigned g_pmh[NB*HD/2];
__device__ __align__(16) unsigned g_qh[NB*HD/2];
__device__ __align__(16) unsigned g_flags[NCTA_SCAN*32];

// ---------------- helpers ----------------
__device__ __forceinline__ unsigned pack_h2(float x, float y){
    __half2 h = __floats2half2_rn(x, y);
    return *reinterpret_cast<unsigned*>(&h);
}
__device__ __forceinline__ float2 h2f2(unsigned u){
    return __half22float2(*reinterpret_cast<const __half2*>(&u));
}
__device__ __forceinline__ uint32_t smem_u32(const void* p){
    uint32_t a; asm("{ .reg .u64 t; cvta.to.shared.u64 t, %1; cvt.u32.u64 %0, t; }"
                    : "=r"(a) : "l"(p)); return a;
}
__device__ __forceinline__ void cpa16(uint32_t dst, const void* src){
    asm volatile("cp.async.cg.shared.global [%0], [%1], 16;" :: "r"(dst), "l"(src));
}
#define CP_COMMIT() asm volatile("cp.async.commit_group;" ::: "memory")
#define CP_WAIT(n)  asm volatile("cp.async.wait_group %0;" :: "n"(n) : "memory")

__device__ __forceinline__ unsigned ldcg_u32(const unsigned* p){
    unsigned v; asm volatile("ld.global.cg.u32 %0, [%1];" : "=r"(v) : "l"(p)); return v;
}
__device__ __forceinline__ void stcg_u32(unsigned* p, unsigned v){
    asm volatile("st.global.cg.u32 [%0], %1;" :: "l"(p), "r"(v) : "memory");
}
__device__ __forceinline__ void ldsm4(unsigned* r, uint32_t addr){
    asm volatile("ldmatrix.sync.aligned.m8n8.x4.shared.b16 {%0,%1,%2,%3}, [%4];"
        : "=r"(r[0]),"=r"(r[1]),"=r"(r[2]),"=r"(r[3]) : "r"(addr));
}
__device__ __forceinline__ void mma16(float* d, const unsigned* a, const unsigned* b){
    asm volatile("mma.sync.aligned.m16n8k16.row.col.f32.f16.f16.f32 "
        "{%0,%1,%2,%3},{%4,%5,%6,%7},{%8,%9},{%0,%1,%2,%3};\n"
        : "+f"(d[0]),"+f"(d[1]),"+f"(d[2]),"+f"(d[3])
        : "r"(a[0]),"r"(a[1]),"r"(a[2]),"r"(a[3]),"r"(b[0]),"r"(b[1]));
}

// 128x128x64 fp16 tile-step (G/F/out)
__device__ __forceinline__ void compute64h(uint32_t aBase, uint32_t bBase,
        const uint32_t* RA, const uint32_t* RB, const uint32_t* TA, const uint32_t* TB,
        float acc[2][8][4]){
    #pragma unroll
    for (int ks = 0; ks < 4; ks++){
        unsigned a0[4], a1[4], bb[4][4];
        ldsm4(a0, aBase + RA[0] + TA[ks]);
        ldsm4(a1, aBase + RA[1] + TA[ks]);
        #pragma unroll
        for (int p = 0; p < 4; p++) ldsm4(bb[p], bBase + RB[p] + TB[ks]);
        #pragma unroll
        for (int mi = 0; mi < 2; mi++){
            const unsigned* a = mi ? a1 : a0;
            #pragma unroll
            for (int p = 0; p < 4; p++){
                unsigned bl[2] = {bb[p][0], bb[p][1]};
                unsigned bh[2] = {bb[p][2], bb[p][3]};
                mma16(acc[mi][2*p],   a, bl);
                mma16(acc[mi][2*p+1], a, bh);
            }
        }
    }
}

// 128x64x64 fp16 tile-step (scan)
__device__ __forceinline__ void compute64h64(uint32_t aBase, uint32_t bBase,
        const uint32_t* RA, const uint32_t* RB, const uint32_t* TA, const uint32_t* TB,
        float acc[2][4][4]){
    #pragma unroll
    for (int ks = 0; ks < 4; ks++){
        unsigned a0[4], a1[4], bb[2][4];
        ldsm4(a0, aBase + RA[0] + TA[ks]);
        ldsm4(a1, aBase + RA[1] + TA[ks]);
        #pragma unroll
        for (int p = 0; p < 2; p++) ldsm4(bb[p], bBase + RB[p] + TB[ks]);
        #pragma unroll
        for (int mi = 0; mi < 2; mi++){
            const unsigned* a = mi ? a1 : a0;
            #pragma unroll
            for (int p = 0; p < 2; p++){
                unsigned bl[2] = {bb[p][0], bb[p][1]};
                unsigned bh[2] = {bb[p][2], bb[p][3]};
                mma16(acc[mi][2*p],   a, bl);
                mma16(acc[mi][2*p+1], a, bh);
            }
        }
    }
}

// fp16 ldmatrix offsets (128-wide warp_n; G/F/out)
#define LDSM_OFFSETS_H() \
    int rowA = warp_m + (lane & 15); \
    uint32_t RA[2] = { (uint32_t)rowA*128u, (uint32_t)(rowA+16)*128u }; \
    uint32_t RB[4]; \
    _Pragma("unroll") for (int p_ = 0; p_ < 4; p_++) \
        RB[p_] = (uint32_t)(warp_n + p_*16 + (lane & 7) + ((lane >> 4) & 1)*8)*128u; \
    uint32_t TA[4], TB[4]; \
    _Pragma("unroll") for (int k_ = 0; k_ < 4; k_++){ \
        TA[k_] = (uint32_t)(((k_*2 + (lane >> 4)) ^ (rowA & 7))*16); \
        TB[k_] = (uint32_t)(((k_*2 + ((lane >> 3) & 1)) ^ (lane & 7))*16); }

// scan variant (warp covers 32x32; 2 B-groups)
#define LDSM_OFFSETS_H64() \
    int rowA = warp_m + (lane & 15); \
    uint32_t RA[2] = { (uint32_t)rowA*128u, (uint32_t)(rowA+16)*128u }; \
    uint32_t RB[2]; \
    _Pragma("unroll") for (int p_ = 0; p_ < 2; p_++) \
        RB[p_] = (uint32_t)(warp_n + p_*16 + (lane & 7) + ((lane >> 4) & 1)*8)*128u; \
    uint32_t TA[4], TB[4]; \
    _Pragma("unroll") for (int k_ = 0; k_ < 4; k_++){ \
        TA[k_] = (uint32_t)(((k_*2 + (lane >> 4)) ^ (rowA & 7))*16); \
        TB[k_] = (uint32_t)(((k_*2 + ((lane >> 3) & 1)) ^ (lane & 7))*16); }

#define ZERO_ACC(acc) { \
    _Pragma("unroll") for (int _i=0;_i<2;_i++) \
    _Pragma("unroll") for (int _j=0;_j<8;_j++) \
    _Pragma("unroll") for (int _k=0;_k<4;_k++) acc[_i][_j][_k]=0.f; }
#define ZERO_ACC4(acc) { \
    _Pragma("unroll") for (int _i=0;_i<2;_i++) \
    _Pragma("unroll") for (int _j=0;_j<4;_j++) \
    _Pragma("unroll") for (int _k=0;_k<4;_k++) acc[_i][_j][_k]=0.f; }

// 256-thread fp16 loader: A 128 rows + B 128 rows, 64 K (128 bytes) per block
#define GEMM_CPH(i_, st_, Ab_, AldB_, Bb_, BldB_) { \
    size_t kb_ = (size_t)(i_)*128; \
    _Pragma("unroll") for (int j = 0; j < 4; j++){ int r_ = rb + j*32; \
        cpa16(sbase + (st_)*TILE_B + r_*128 + swz16, \
              (Ab_) + (size_t)r_*(AldB_) + kb_ + u16); \
        cpa16(sbase + (3 + (st_))*TILE_B + r_*128 + swz16, \
              (Bb_) + (size_t)r_*(BldB_) + kb_ + u16); } CP_COMMIT(); }

// ---------------- K0: per-replay init ----------------
__global__ void k_init(){
    int i = blockIdx.x * blockDim.x + threadIdx.x;
    if (i < NCTA_SCAN*32) g_flags[i] = 0u;
    if (i < NROW) g_Glogit[i] = 0.f;
    if (i < NB*HD/2) g_Ch[i] = 0u;
    if (i < NB*HD) g_Otmp[i] = 0.f;
}

// ---------------- Kc: fp32 -> fp16 bulk convert ----------------
__global__ void k_cvt_h(const float4* __restrict__ src, uint2* __restrict__ dst, int n4){
    for (int i = blockIdx.x*blockDim.x + threadIdx.x; i < n4; i += gridDim.x*blockDim.x){
        float4 v = src[i];
        dst[i] = make_uint2(pack_h2(v.x, v.y), pack_h2(v.z, v.w));
    }
}

// ---------------- Kz: build z (fp16) ----------------
__global__ void k_zb_h(const float* __restrict__ facts, const float* __restrict__ q,
                       const float* __restrict__ pm){
    int row = blockIdx.x;           // bt*NS + s
    int bt = row >> 7;
    int t = threadIdx.x;
    float4 f  = *reinterpret_cast<const float4*>(facts + (size_t)row*HD + t*4);
    float4 qv = *reinterpret_cast<const float4*>(q  + (size_t)bt*HD + t*4);
    float4 mv = *reinterpret_cast<const float4*>(pm + (size_t)bt*HD + t*4);
    char* zr = reinterpret_cast<char*>(g_zh) + (size_t)row*8192;
    *reinterpret_cast<uint2*>(zr + 0*2048 + t*8) =
        make_uint2(pack_h2(f.x*qv.x, f.y*qv.y), pack_h2(f.z*qv.z, f.w*qv.w));
    *reinterpret_cast<uint2*>(zr + 1*2048 + t*8) =
        make_uint2(pack_h2(f.x*mv.x, f.y*mv.y), pack_h2(f.z*mv.z, f.w*mv.w));
    *reinterpret_cast<uint2*>(zr + 2*2048 + t*8) =
        make_uint2(pack_h2(fabsf(f.x-qv.x), fabsf(f.y-qv.y)), pack_h2(fabsf(f.z-qv.z), fabsf(f.w-qv.w)));
    *reinterpret_cast<uint2*>(zr + 3*2048 + t*8) =
        make_uint2(pack_h2(fabsf(f.x-mv.x), fabsf(f.y-mv.y)), pack_h2(fabsf(f.z-mv.z), fabsf(f.w-mv.w)));
}

// ================= K1: G logits =================
__global__ void __launch_bounds__(256,2) kA_G(
        const float* __restrict__ bz1, const float* __restrict__ Wz2){
    extern __shared__ unsigned us[];
    uint32_t sbase = smem_u32(us);
    int tid = threadIdx.x, wid = tid >> 5, lane = tid & 31;
    int lg = lane >> 2, lk = lane & 3;
    int warp_m = (wid >> 1) * 32, warp_n = (wid & 1) * 64;
    int nt = blockIdx.x, bt = blockIdx.y;
    int u16 = (tid & 7) * 16, rb = tid >> 3;
    uint32_t swz16 = (uint32_t)(((tid & 7) ^ (rb & 7)) * 16);
    LDSM_OFFSETS_H();
    const char* Ab = reinterpret_cast<const char*>(g_zh) + (size_t)bt*NS*8192;
    const char* Bb = reinterpret_cast<const char*>(g_Wz1h) + (size_t)(nt*128)*8192;
    float acc[2][8][4]; ZERO_ACC(acc);

    const int NBLK = 64;
    GEMM_CPH(0, 0, Ab, 8192, Bb, 8192);
    GEMM_CPH(1, 1, Ab, 8192, Bb, 8192);
    int st = 0;
    for (int i = 0; i < NBLK; i++){
        CP_WAIT(1);
        __syncthreads();
        if (i + 2 < NBLK){
            int st2 = st + 2; if (st2 >= 3) st2 -= 3;
            GEMM_CPH(i+2, st2, Ab, 8192, Bb, 8192);
        }
        compute64h(sbase + st*TILE_B, sbase + (3+st)*TILE_B, RA, RB, TA, TB, acc);
        if (++st == 3) st = 0;
    }

    float rs[4] = {0.f, 0.f, 0.f, 0.f};
    #pragma unroll
    for (int mi = 0; mi < 2; mi++)
        #pragma unroll
        for (int ni = 0; ni < 8; ni++){
            int c0 = nt*128 + warp_n + ni*8 + lk*2;
            float w0 = Wz2[c0], w1 = Wz2[c0+1];
            float z0 = bz1[c0], z1 = bz1[c0+1];
            rs[mi*2+0] += tanhf(acc[mi][ni][0]+z0)*w0 + tanhf(acc[mi][ni][1]+z1)*w1;
            rs[mi*2+1] += tanhf(acc[mi][ni][2]+z0)*w0 + tanhf(acc[mi][ni][3]+z1)*w1;
        }
    #pragma unroll
    for (int r = 0; r < 4; r++){
        rs[r] += __shfl_xor_sync(0xffffffffu, rs[r], 1);
        rs[r] += __shfl_xor_sync(0xffffffffu, rs[r], 2);
    }
    if (lk == 0){
        int s0 = warp_m + lg;
        atomicAdd(&g_Glogit[bt*NS + s0     ], rs[0]);
        atomicAdd(&g_Glogit[bt*NS + s0 + 8 ], rs[1]);
        atomicAdd(&g_Glogit[bt*NS + s0 + 16], rs[2]);
        atomicAdd(&g_Glogit[bt*NS + s0 + 24], rs[3]);
    }
}

// ================= K3: FR/FW (fp16 outputs) =================
__global__ void __launch_bounds__(256,2) kA_F(
        const float* __restrict__ br, const float* __restrict__ bw){
    extern __shared__ unsigned us[];
    uint32_t sbase = smem_u32(us);
    int tid = threadIdx.x, wid = tid >> 5, lane = tid & 31;
    int lg = lane >> 2, lk = lane & 3;
    int warp_m = (wid >> 1) * 32, warp_n = (wid & 1) * 64;
    int nt = blockIdx.x, bt = blockIdx.y, which = blockIdx.z;
    const unsigned* Wsel = which ? g_Wh : g_Wrh;
    const float*    bsel = which ? bw : br;
    unsigned* Outh = which ? g_FWh : g_FRh;
    int u16 = (tid & 7) * 16, rb = tid >> 3;
    uint32_t swz16 = (uint32_t)(((tid & 7) ^ (rb & 7)) * 16);
    LDSM_OFFSETS_H();
    const char* Ab = reinterpret_cast<const char*>(g_fh) + (size_t)bt*NS*2048;
    const char* Bb = reinterpret_cast<const char*>(Wsel) + (size_t)(nt*128)*2048;
    float acc[2][8][4]; ZERO_ACC(acc);

    const int NBLK = 16;
    GEMM_CPH(0, 0, Ab, 2048, Bb, 2048);
    GEMM_CPH(1, 1, Ab, 2048, Bb, 2048);
    int st = 0;
    for (int i = 0; i < NBLK; i++){
        CP_WAIT(1);
        __syncthreads();
        if (i + 2 < NBLK){
            int st2 = st + 2; if (st2 >= 3) st2 -= 3;
            GEMM_CPH(i+2, st2, Ab, 2048, Bb, 2048);
        }
        compute64h(sbase + st*TILE_B, sbase + (3+st)*TILE_B, RA, RB, TA, TB, acc);
        if (++st == 3) st = 0;
    }

    #pragma unroll
    for (int mi = 0; mi < 2; mi++){
        int r0 = warp_m + mi*16 + lg;   // s index
        #pragma unroll
        for (int ni = 0; ni < 8; ni++){
            int h = nt*128 + warp_n + ni*8 + lk*2;
            float b0 = bsel[h], b1 = bsel[h+1];
            Outh[((size_t)r0*(NB*HD) + (size_t)bt*HD + h) >> 1] =
                pack_h2(acc[mi][ni][0]+b0, acc[mi][ni][1]+b1);
            Outh[((size_t)(r0+8)*(NB*HD) + (size_t)bt*HD + h) >> 1] =
                pack_h2(acc[mi][ni][2]+b0, acc[mi][ni][3]+b1);
        }
    }
}

// ---------------- K2: softmax ----------------
__global__ void k_softmax(){
    int bt = blockIdx.x, t = threadIdx.x;
    float v = g_Glogit[bt*NS + t];
    __shared__ float sm_[4], ss[4];
    float mx = v;
    #pragma unroll
    for (int o = 16; o; o >>= 1) mx = fmaxf(mx, __shfl_xor_sync(0xffffffffu, mx, o));
    if ((t & 31) == 0) sm_[t >> 5] = mx;
    __syncthreads();
    mx = fmaxf(fmaxf(sm_[0], sm_[1]), fmaxf(sm_[2], sm_[3]));
    float e = __expf(v - mx);
    float sum = e;
    #pragma unroll
    for (int o = 16; o; o >>= 1) sum += __shfl_xor_sync(0xffffffffu, sum, o);
    if ((t & 31) == 0) ss[t >> 5] = sum;
    __syncthreads();
    sum = ss[0] + ss[1] + ss[2] + ss[3];
    g_Gt[t*NB + bt] = e / sum;
}

// ---------------- K4: persistent scan (32 N-tiles x 4 K-slices, fp16 partials) ----------------
__device__ __forceinline__ void gsync(unsigned step, int tid, int cta){
    __syncthreads();
    if (tid == 0){
        __threadfence();
        stcg_u32(&g_flags[cta*32], step);
    }
    if (tid < NCTA_SCAN){
        while (ldcg_u32(&g_flags[tid*32]) < step) { }
    }
    __threadfence();
    __syncthreads();
}
__device__ __forceinline__ float gru_upd(float fr, float fw, float y1, float y2,
                                         float b_ur, float b_u, float c, float g){
    float r  = 1.f / (1.f + __expf(-(fr + y1 + b_ur)));
    float ht = tanhf(fw + r * (y2 + b_u));
    return g * ht + (1.f - g) * c;
}

__global__ void __launch_bounds__(256,1) kA_scan(
        const float* __restrict__ bur, const float* __restrict__ bu){
    extern __shared__ unsigned us[];   // A subs: 4 x TILE_B; B resident: 4 x TILE_S at 4*TILE_B
    uint32_t sbase = smem_u32(us);
    int cta = blockIdx.x, tid = threadIdx.x;
    int wid = tid >> 5, lane = tid & 31, lg = lane >> 2, lk = lane & 3;
    int warp_m = (wid & 3) * 32, warp_n = (wid >> 2) * 32;
    int u16 = (tid & 7) * 16, rb = tid >> 3;
    uint32_t swz16 = (uint32_t)(((tid & 7) ^ (rb & 7)) * 16);
    LDSM_OFFSETS_H64();
    int nt  = cta >> 2;             // 0..31: 0-15 Y1 (Ur), 16-31 Y2 (U)
    int knt = cta & 3;              // K slice
    int kcb = knt * 256;            // K base (halves)
    const unsigned* Wsel = (nt < 16) ? g_Urh : g_Uh;
    int nbase = (nt & 15) * 64;
    unsigned* P = g_parth + (size_t)cta * 4096;   // 128x64 halves = 4096 unsigned
    const char* Wb = reinterpret_cast<const char*>(Wsel) + (size_t)nbase*2048 + kcb*2;
    const char* Cb = reinterpret_cast<const char*>(g_Ch) + kcb*2;
    uint32_t bBase0 = sbase + 4*TILE_B;

    // resident fp16 weights: 4 chunks of 64 rows x 64 K
    #pragma unroll
    for (int j = 0; j < 8; j++){
        int c = j >> 1, n = rb + (j & 1)*32;
        cpa16(bBase0 + c*TILE_S + n*128 + swz16,
              Wb + (size_t)n*2048 + c*128 + u16);
    }
    CP_COMMIT();
    CP_WAIT(0);
    __syncthreads();

    int e  = (cta*256 + tid) * 4;   // 4 consecutive h per thread
    int eb = e >> 10, eh = e & (HD-1);
    int nt1 = eh >> 6, hm = eh & 63;
    float4 vur = *reinterpret_cast<const float4*>(bur + eh);
    float4 vu  = *reinterpret_cast<const float4*>(bu + eh);
    float4 creg = make_float4(0.f, 0.f, 0.f, 0.f);
    size_t fidx = 0;  // ((s*NB+eb)*HD + eh)/2 incremental

    unsigned bar = 0;
    for (int s = 0; s < NS; s++){
        size_t fi = (((size_t)s*NB + eb)*HD + eh) >> 1;
        uint2 fru = *reinterpret_cast<const uint2*>(g_FRh + fi);
        uint2 fwu = *reinterpret_cast<const uint2*>(g_FWh + fi);
        float gg = g_Gt[s*NB + eb];

        // phase A: C slice (fp16), 4 sub-tiles of 64K, resident weights
        #pragma unroll
        for (int sg = 0; sg < 4; sg++){
            #pragma unroll
            for (int j = 0; j < 4; j++){
                int r = rb + j*32;
                cpa16(sbase + sg*TILE_B + r*128 + swz16,
                      Cb + (size_t)r*2048 + sg*128 + u16);
            }
            CP_COMMIT();
        }
        float acc[2][4][4]; ZERO_ACC4(acc);
        #pragma unroll
        for (int sub = 0; sub < 4; sub++){
            if (sub == 0)      CP_WAIT(3);
            else if (sub == 1) CP_WAIT(2);
            else if (sub == 2) CP_WAIT(1);
            else               CP_WAIT(0);
            __syncthreads();
            compute64h64(sbase + sub*TILE_B, bBase0 + sub*TILE_S, RA, RB, TA, TB, acc);
        }
        // store fp16 partials (128x64 per CTA)
        #pragma unroll
        for (int mi = 0; mi < 2; mi++){
            int r0 = warp_m + mi*16 + lg;
            #pragma unroll
            for (int ni = 0; ni < 4; ni++){
                int c2 = (warp_n + ni*8) / 2 + lk;   // packed col index
                stcg_u32(&P[r0*32 + c2],     pack_h2(acc[mi][ni][0], acc[mi][ni][1]));
                stcg_u32(&P[(r0+8)*32 + c2], pack_h2(acc[mi][ni][2], acc[mi][ni][3]));
            }
        }
        gsync(++bar, tid, cta);

        // phase B: reduce 4 fp16 partials per y, GRU update
        float4 y1 = make_float4(0,0,0,0), y2 = make_float4(0,0,0,0);
        int pidx = eb*32 + (hm >> 1);
        #pragma unroll
        for (int kk = 0; kk < 4; kk++){
            uint2 p1 = *reinterpret_cast<const uint2*>(
                g_parth + (size_t)(nt1*4 + kk)*4096 + pidx);
            uint2 p2 = *reinterpret_cast<const uint2*>(
                g_parth + (size_t)((nt1+16)*4 + kk)*4096 + pidx);
            float2 a = h2f2(p1.x), b = h2f2(p1.y);
            y1.x += a.x; y1.y += a.y; y1.z += b.x; y1.w += b.y;
            float2 c = h2f2(p2.x), d = h2f2(p2.y);
            y2.x += c.x; y2.y += c.y; y2.z += d.x; y2.w += d.y;
        }
        float2 fr0 = h2f2(fru.x), fr1 = h2f2(fru.y);
        float2 fw0 = h2f2(fwu.x), fw1 = h2f2(fwu.y);
        creg.x = gru_upd(fr0.x, fw0.x, y1.x, y2.x, vur.x, vu.x, creg.x, gg);
        creg.y = gru_upd(fr0.y, fw0.y, y1.y, y2.y, vur.y, vu.y, creg.y, gg);
        creg.z = gru_upd(fr1.x, fw1.x, y1.z, y2.z, vur.z, vu.z, creg.z, gg);
        creg.w = gru_upd(fr1.y, fw1.y, y1.w, y2.w, vur.w, vu.w, creg.w, gg);
        __stcg(reinterpret_cast<uint2*>(g_Ch + (e >> 1)),
               make_uint2(pack_h2(creg.x, creg.y), pack_h2(creg.z, creg.w)));
        gsync(++bar, tid, cta);
        (void)fidx;
    }
}

// ---------------- K5: final GEMM (pipelined split-K) ----------------
__global__ void __launch_bounds__(256,2) kA_out(){
    extern __shared__ unsigned us[];
    uint32_t sbase = smem_u32(us);
    int tid = threadIdx.x, wid = tid >> 5, lane = tid & 31;
    int lg = lane >> 2, lk = lane & 3;
    int warp_m = (wid >> 1) * 32, warp_n = (wid & 1) * 64;
    int nt = blockIdx.x, ks = blockIdx.y;   // ks in [0,12)
    int u16 = (tid & 7) * 16, rb = tid >> 3;
    uint32_t swz16 = (uint32_t)(((tid & 7) ^ (rb & 7)) * 16);
    LDSM_OFFSETS_H();
    int seg = ks >> 2;
    const unsigned* Asel = (seg == 0) ? g_pmh : (seg == 1 ? g_Ch : g_qh);
    const char* Ab = reinterpret_cast<const char*>(Asel) + (ks & 3) * 512;
    const char* Bb = reinterpret_cast<const char*>(g_Wmh) + (size_t)(nt*128)*6144 + ks*512;
    float acc[2][8][4]; ZERO_ACC(acc);

    const int NBLK = 4;
    GEMM_CPH(0, 0, Ab, 2048, Bb, 6144);
    GEMM_CPH(1, 1, Ab, 2048, Bb, 6144);
    int st = 0;
    for (int i = 0; i < NBLK; i++){
        CP_WAIT(1);
        __syncthreads();
        if (i + 2 < NBLK){
            int st2 = st + 2; if (st2 >= 3) st2 -= 3;
            GEMM_CPH(i+2, st2, Ab, 2048, Bb, 6144);
        }
        compute64h(sbase + st*TILE_B, sbase + (3+st)*TILE_B, RA, RB, TA, TB, acc);
        if (++st == 3) st = 0;
    }
    #pragma unroll
    for (int mi = 0; mi < 2; mi++){
        int r0 = warp_m + mi*16 + lg;
        #pragma unroll
        for (int ni = 0; ni < 8; ni++){
            int h = nt*128 + warp_n + ni*8 + lk*2;
            atomicAdd(&g_Otmp[(size_t)r0*HD + h     ], acc[mi][ni][0]);
            atomicAdd(&g_Otmp[(size_t)r0*HD + h + 1 ], acc[mi][ni][1]);
            atomicAdd(&g_Otmp[(size_t)(r0+8)*HD + h    ], acc[mi][ni][2]);
            atomicAdd(&g_Otmp[(size_t)(r0+8)*HD + h + 1], acc[mi][ni][3]);
        }
    }
}

// ---------------- K6: bias + relu ----------------
__global__ void k_finish(const float* __restrict__ bm, float* __restrict__ out){
    int i = blockIdx.x * blockDim.x + threadIdx.x;
    if (i < NB*HD){
        float v = g_Otmp[i] + bm[i & (HD-1)];
        out[i] = fmaxf(v, 0.f);
    }
}

// ---------------- launch ----------------
extern "C" void kernel_launch(void* const* d_in, const int* in_sizes, int n_in,
                              void* d_out, int out_size){
    (void)in_sizes; (void)n_in; (void)out_size;
    const float* facts     = (const float*)d_in[0];
    const float* questions = (const float*)d_in[1];
    const float* prevM     = (const float*)d_in[2];
    const float* Wr  = (const float*)d_in[3];
    const float* br  = (const float*)d_in[4];
    const float* Ur  = (const float*)d_in[5];
    const float* bur = (const float*)d_in[6];
    const float* W   = (const float*)d_in[7];
    const float* bw  = (const float*)d_in[8];
    const float* U   = (const float*)d_in[9];
    const float* bu  = (const float*)d_in[10];
    const float* Wz1 = (const float*)d_in[11];
    const float* bz1 = (const float*)d_in[12];
    const float* Wz2 = (const float*)d_in[13];
    // d_in[14] = bz2: softmax shift-invariant, cancels.
    const float* Wm  = (const float*)d_in[15];
    const float* bm  = (const float*)d_in[16];
    float* out = (float*)d_out;

    static int attr_done = 0;
    if (!attr_done){
        cudaFuncSetAttribute(kA_G,    cudaFuncAttributeMaxDynamicSharedMemorySize, GEMM_SMEM);
        cudaFuncSetAttribute(kA_F,    cudaFuncAttributeMaxDynamicSharedMemorySize, GEMM_SMEM);
        cudaFuncSetAttribute(kA_scan, cudaFuncAttributeMaxDynamicSharedMemorySize, SCAN_SMEM);
        cudaFuncSetAttribute(kA_out,  cudaFuncAttributeMaxDynamicSharedMemorySize, GEMM_SMEM);
        attr_done = 1;
    }

    unsigned *dWz1h, *dWrh, *dWh, *dUrh, *dUh, *dfh, *dWmh, *dpmh, *dqh;
    cudaGetSymbolAddress((void**)&dWz1h, g_Wz1h);
    cudaGetSymbolAddress((void**)&dWrh,  g_Wrh);
    cudaGetSymbolAddress((void**)&dWh,   g_Wh);
    cudaGetSymbolAddress((void**)&dUrh,  g_Urh);
    cudaGetSymbolAddress((void**)&dUh,   g_Uh);
    cudaGetSymbolAddress((void**)&dfh,   g_fh);
    cudaGetSymbolAddress((void**)&dWmh,  g_Wmh);
    cudaGetSymbolAddress((void**)&dpmh,  g_pmh);
    cudaGetSymbolAddress((void**)&dqh,   g_qh);

    k_init<<<512, 256>>>();
    k_cvt_h<<<2048, 256>>>((const float4*)facts, (uint2*)dfh,   (NB*NS*HD)/4);
    k_cvt_h<<<1024, 256>>>((const float4*)Wz1,   (uint2*)dWz1h, (HD*4*HD)/4);
    k_cvt_h<<<512, 256>>>((const float4*)Wr,     (uint2*)dWrh,  (HD*HD)/4);
    k_cvt_h<<<512, 256>>>((const float4*)W,      (uint2*)dWh,   (HD*HD)/4);
    k_cvt_h<<<512, 256>>>((const float4*)Ur,     (uint2*)dUrh,  (HD*HD)/4);
    k_cvt_h<<<512, 256>>>((const float4*)U,      (uint2*)dUh,   (HD*HD)/4);
    k_cvt_h<<<1024, 256>>>((const float4*)Wm,    (uint2*)dWmh,  (HD*3*HD)/4);
    k_cvt_h<<<128, 256>>>((const float4*)prevM,  (uint2*)dpmh,  (NB*HD)/4);
    k_cvt_h<<<128, 256>>>((const float4*)questions, (uint2*)dqh, (NB*HD)/4);
    k_zb_h<<<NROW, 256>>>(facts, questions, prevM);
    dim3 gG(8, 128);
    kA_G<<<gG, 256, GEMM_SMEM>>>(bz1, Wz2);
    k_softmax<<<128, 128>>>();
    dim3 gF(8, 128, 2);
    kA_F<<<gF, 256, GEMM_SMEM>>>(br, bw);
    kA_scan<<<NCTA_SCAN, 256, SCAN_SMEM>>>(bur, bu);
    dim3 gO(8, 12);
    kA_out<<<gO, 256, GEMM_SMEM>>>();
    k_finish<<<512, 256>>>(bm, out);
}